// round 8
// baseline (speedup 1.0000x reference)
#include <cuda_runtime.h>
#include <cuda_bf16.h>
#include <math.h>
#include <stdint.h>

// Problem constants
#define D_MODEL 1024
#define N_HEADS 16
#define D_HEAD  64
#define BATCH   4
#define SEQ     512
#define M_TOK   (BATCH * SEQ)       // 2048
#define QKV_N   (3 * D_MODEL)       // 3072
#define BHN     (BATCH * N_HEADS)   // 64
#define QS      (BHN * SEQ * D_HEAD) // 2097152

// ---------------- device scratch (no runtime allocation allowed) ----------------
__device__ float g_rope_cos[SEQ * D_HEAD];
__device__ float g_rope_sin[SEQ * D_HEAD];
__device__ float g_qkv_r[(size_t)M_TOK * QKV_N];
__device__ float g_qkv_i[(size_t)M_TOK * QKV_N];

// bf16 hi/lo splits for projection GEMMs (r=real, i=imag, s=real+imag for Karatsuba)
#define XN   (M_TOK * D_MODEL)      // 2097152
#define WQN  (QKV_N * D_MODEL)      // 3145728
#define WON  (D_MODEL * D_MODEL)    // 1048576
__device__ __nv_bfloat16 g_xrH[XN],  g_xrL[XN],  g_xiH[XN],  g_xiL[XN],  g_xsH[XN],  g_xsL[XN];
__device__ __nv_bfloat16 g_wqrH[WQN], g_wqrL[WQN], g_wqiH[WQN], g_wqiL[WQN], g_wqsH[WQN], g_wqsL[WQN];
__device__ __nv_bfloat16 g_worH[WON], g_worL[WON], g_woiH[WON], g_woiL[WON], g_wosH[WON], g_wosL[WON];
__device__ __nv_bfloat16 g_arH[XN],  g_arL[XN],  g_aiH[XN],  g_aiL[XN],  g_asH[XN],  g_asL[XN];

// bf16 hi/lo splits for attention (written by rope_apply)
// Q, K: [bh][s][d] token-major.  V: [bh][d][s] dim-major (transposed, B-frag ready).
__device__ __nv_bfloat16 g_QrH[QS], g_QrL[QS], g_QiH[QS], g_QiL[QS];
__device__ __nv_bfloat16 g_KrH[QS], g_KrL[QS], g_KiH[QS], g_KiL[QS];
__device__ __nv_bfloat16 g_VrH[QS], g_VrL[QS], g_ViH[QS], g_ViL[QS];

// ================= PTX helpers (baseline ISA only — no tcgen05) =================
__device__ __forceinline__ uint32_t smem_u32(const void* p) {
    uint32_t a;
    asm("{ .reg .u64 t; cvta.to.shared.u64 t, %1; cvt.u32.u64 %0, t; }" : "=r"(a) : "l"(p));
    return a;
}
__device__ __forceinline__ void cp_async16(uint32_t dst, const void* src) {
    asm volatile("cp.async.cg.shared.global [%0], [%1], 16;" :: "r"(dst), "l"(src));
}
__device__ __forceinline__ void cp_commit() {
    asm volatile("cp.async.commit_group;" ::: "memory");
}
template <int N> __device__ __forceinline__ void cp_wait() {
    asm volatile("cp.async.wait_group %0;" :: "n"(N) : "memory");
}
__device__ __forceinline__ void ldsm_x4(uint32_t* r, uint32_t a) {
    asm volatile("ldmatrix.sync.aligned.m8n8.x4.shared.b16 {%0,%1,%2,%3}, [%4];"
                 : "=r"(r[0]), "=r"(r[1]), "=r"(r[2]), "=r"(r[3]) : "r"(a));
}
__device__ __forceinline__ void ldsm_x2(uint32_t* r, uint32_t a) {
    asm volatile("ldmatrix.sync.aligned.m8n8.x2.shared.b16 {%0,%1}, [%2];"
                 : "=r"(r[0]), "=r"(r[1]) : "r"(a));
}
// D += A(16x16 bf16, row) * B(16x8 bf16, col), fp32 accumulate
__device__ __forceinline__ void mma_bf16(float* c, const uint32_t* a, const uint32_t* b) {
    asm volatile(
        "mma.sync.aligned.m16n8k16.row.col.f32.bf16.bf16.f32 "
        "{%0,%1,%2,%3}, {%4,%5,%6,%7}, {%8,%9}, {%0,%1,%2,%3};"
        : "+f"(c[0]), "+f"(c[1]), "+f"(c[2]), "+f"(c[3])
        : "r"(a[0]), "r"(a[1]), "r"(a[2]), "r"(a[3]), "r"(b[0]), "r"(b[1]));
}
__device__ __forceinline__ void bsplit(float v, __nv_bfloat16& h, __nv_bfloat16& l) {
    h = __float2bfloat16_rn(v);
    l = __float2bfloat16_rn(v - __bfloat162float(h));
}
__device__ __forceinline__ uint32_t packbf2(__nv_bfloat16 a, __nv_bfloat16 b) {
    __nv_bfloat162 t{a, b};
    return *reinterpret_cast<uint32_t*>(&t);
}
#define SGNX2 0x80008000u

// ---------------- kernel 1: RoPE rotor table ----------------
__global__ void rope_table_kernel() {
    int i = blockIdx.x * blockDim.x + threadIdx.x;
    if (i >= SEQ * D_HEAD) return;
    int s = i / D_HEAD;
    int d = i % D_HEAD;
    float inv_freq = powf(10000.0f, -(float)d / (float)D_HEAD);
    float ang = (float)s * inv_freq;
    float sn, cs;
    sincosf(ang, &sn, &cs);
    g_rope_cos[i] = cs;
    g_rope_sin[i] = sn;
}

// ---------------- kernel 1b: complex hi/lo split (re, im, re+im) ----------------
__global__ void split2_kernel(const float* __restrict__ re, const float* __restrict__ im,
                              __nv_bfloat16* __restrict__ rH, __nv_bfloat16* __restrict__ rL,
                              __nv_bfloat16* __restrict__ iH, __nv_bfloat16* __restrict__ iL,
                              __nv_bfloat16* __restrict__ sH, __nv_bfloat16* __restrict__ sL,
                              int n4) {
    int i = blockIdx.x * blockDim.x + threadIdx.x;
    if (i >= n4) return;
    float4 vr = ((const float4*)re)[i];
    float4 vi = ((const float4*)im)[i];
    __nv_bfloat16 h0, h1, h2, h3, l0, l1, l2, l3;

    bsplit(vr.x, h0, l0); bsplit(vr.y, h1, l1); bsplit(vr.z, h2, l2); bsplit(vr.w, h3, l3);
    ((uint32_t*)rH)[i * 2 + 0] = packbf2(h0, h1);
    ((uint32_t*)rH)[i * 2 + 1] = packbf2(h2, h3);
    ((uint32_t*)rL)[i * 2 + 0] = packbf2(l0, l1);
    ((uint32_t*)rL)[i * 2 + 1] = packbf2(l2, l3);

    bsplit(vi.x, h0, l0); bsplit(vi.y, h1, l1); bsplit(vi.z, h2, l2); bsplit(vi.w, h3, l3);
    ((uint32_t*)iH)[i * 2 + 0] = packbf2(h0, h1);
    ((uint32_t*)iH)[i * 2 + 1] = packbf2(h2, h3);
    ((uint32_t*)iL)[i * 2 + 0] = packbf2(l0, l1);
    ((uint32_t*)iL)[i * 2 + 1] = packbf2(l2, l3);

    bsplit(vr.x + vi.x, h0, l0); bsplit(vr.y + vi.y, h1, l1);
    bsplit(vr.z + vi.z, h2, l2); bsplit(vr.w + vi.w, h3, l3);
    ((uint32_t*)sH)[i * 2 + 0] = packbf2(h0, h1);
    ((uint32_t*)sH)[i * 2 + 1] = packbf2(h2, h3);
    ((uint32_t*)sL)[i * 2 + 0] = packbf2(l0, l1);
    ((uint32_t*)sL)[i * 2 + 1] = packbf2(l2, l3);
}

// ---------------- kernel 2: Karatsuba mma.sync complex GEMM  C = A @ B^T ----------------
// P1 = Ar*Br, P2 = Ai*Bi, P3 = (Ar+Ai)*(Br+Bi);  Cre = P1-P2, Cim = P3-P1-P2.
// Each product = 3 split-HMMA (HH, HL, LH). 9 HMMA per micro-tile (was 12).
// CTA tile 128x64, K-stage 32, double-buffered cp.async, 8 warps (4m x 2n).
#define GBM 128
#define GBN 64
#define GBK 32
#define GPITCHB 80
#define A_COMP_B (GBM * GPITCHB)              // 10240
#define B_COMP_B (GBN * GPITCHB)              // 5120
#define STAGE_B  (6 * A_COMP_B + 6 * B_COMP_B) // 92160
#define G_SMEM   (2 * STAGE_B)                 // 184320

__global__ __launch_bounds__(256, 1) void cgemm_tc_kernel(
    const __nv_bfloat16* __restrict__ ArH, const __nv_bfloat16* __restrict__ ArL,
    const __nv_bfloat16* __restrict__ AiH, const __nv_bfloat16* __restrict__ AiL,
    const __nv_bfloat16* __restrict__ AsH, const __nv_bfloat16* __restrict__ AsL,
    const __nv_bfloat16* __restrict__ BrH, const __nv_bfloat16* __restrict__ BrL,
    const __nv_bfloat16* __restrict__ BiH, const __nv_bfloat16* __restrict__ BiL,
    const __nv_bfloat16* __restrict__ BsH, const __nv_bfloat16* __restrict__ BsL,
    float* __restrict__ Cre, float* __restrict__ Cim,
    int N, int K)
{
    extern __shared__ __align__(128) char smem[];
    const uint32_t sb = smem_u32(smem);
    const int tid = threadIdx.x;
    const int lane = tid & 31;
    const int wid = tid >> 5;
    const int wm = wid & 3;
    const int wn = wid >> 2;
    const int m0 = blockIdx.y * GBM;
    const int n0 = blockIdx.x * GBN;

    const __nv_bfloat16* Ap[6] = {ArH, ArL, AiH, AiL, AsH, AsL};
    const __nv_bfloat16* Bp[6] = {BrH, BrL, BiH, BiL, BsH, BsL};

    auto load_stage = [&](int st, int k0) {
        uint32_t base = sb + st * STAGE_B;
#pragma unroll
        for (int i = 0; i < 12; i++) {                // A: 3072 16B chunks
            int idx = tid + i * 256;
            int comp = idx >> 9;
            int rem = idx & 511;
            int row = rem >> 2;
            int ch = rem & 3;
            cp_async16(base + comp * A_COMP_B + row * GPITCHB + ch * 16,
                       Ap[comp] + (size_t)(m0 + row) * K + k0 + ch * 8);
        }
        uint32_t bbase = base + 6 * A_COMP_B;
#pragma unroll
        for (int i = 0; i < 6; i++) {                 // B: 1536 16B chunks
            int idx = tid + i * 256;
            int comp = idx >> 8;
            int rem = idx & 255;
            int row = rem >> 2;
            int ch = rem & 3;
            cp_async16(bbase + comp * B_COMP_B + row * GPITCHB + ch * 16,
                       Bp[comp] + (size_t)(n0 + row) * K + k0 + ch * 8);
        }
        cp_commit();
    };

    float P[3][2][4][4];
#pragma unroll
    for (int p = 0; p < 3; p++)
#pragma unroll
        for (int mt = 0; mt < 2; mt++)
#pragma unroll
            for (int nt = 0; nt < 4; nt++)
#pragma unroll
                for (int q = 0; q < 4; q++) P[p][mt][nt][q] = 0.f;

    const int NC = K / GBK;
    load_stage(0, 0);

    for (int c = 0; c < NC; c++) {
        if (c + 1 < NC) { load_stage((c + 1) & 1, (c + 1) * GBK); cp_wait<1>(); }
        else            { cp_wait<0>(); }
        __syncthreads();

        const uint32_t abase = sb + (c & 1) * STAGE_B;
        const uint32_t bbase = abase + 6 * A_COMP_B;

#pragma unroll
        for (int ks = 0; ks < 2; ks++) {
#pragma unroll
            for (int p = 0; p < 3; p++) {
                uint32_t aH[2][4], aL[2][4];
#pragma unroll
                for (int mt = 0; mt < 2; mt++) {
                    uint32_t ra = (uint32_t)(wm * 32 + mt * 16 + (lane & 15)) * GPITCHB
                                  + ks * 32 + (lane >> 4) * 16;
                    ldsm_x4(aH[mt], abase + (2 * p + 0) * A_COMP_B + ra);
                    ldsm_x4(aL[mt], abase + (2 * p + 1) * A_COMP_B + ra);
                }
                uint32_t bH[4][2], bL[4][2];
#pragma unroll
                for (int nt = 0; nt < 4; nt++) {
                    int c16 = lane & 15;
                    uint32_t rb = (uint32_t)(wn * 32 + nt * 8 + (c16 & 7)) * GPITCHB
                                  + ks * 32 + (c16 >> 3) * 16;
                    ldsm_x2(bH[nt], bbase + (2 * p + 0) * B_COMP_B + rb);
                    ldsm_x2(bL[nt], bbase + (2 * p + 1) * B_COMP_B + rb);
                }
#pragma unroll
                for (int mt = 0; mt < 2; mt++)
#pragma unroll
                    for (int nt = 0; nt < 4; nt++) {
                        float* acc = P[p][mt][nt];
                        mma_bf16(acc, aH[mt], bH[nt]);
                        mma_bf16(acc, aH[mt], bL[nt]);
                        mma_bf16(acc, aL[mt], bH[nt]);
                    }
            }
        }
        __syncthreads();
    }

    // epilogue: re = P1-P2, im = P3-P1-P2
#pragma unroll
    for (int mt = 0; mt < 2; mt++) {
        int row0 = m0 + wm * 32 + mt * 16 + (lane >> 2);
#pragma unroll
        for (int nt = 0; nt < 4; nt++) {
            int col = n0 + wn * 32 + nt * 8 + (lane & 3) * 2;
            float re[4], im[4];
#pragma unroll
            for (int q = 0; q < 4; q++) {
                float p1 = P[0][mt][nt][q], p2 = P[1][mt][nt][q], p3 = P[2][mt][nt][q];
                re[q] = p1 - p2;
                im[q] = p3 - p1 - p2;
            }
            *(float2*)(Cre + (size_t)row0 * N + col) = {re[0], re[1]};
            *(float2*)(Cre + (size_t)(row0 + 8) * N + col) = {re[2], re[3]};
            *(float2*)(Cim + (size_t)row0 * N + col) = {im[0], im[1]};
            *(float2*)(Cim + (size_t)(row0 + 8) * N + col) = {im[2], im[3]};
        }
    }
}

// ---------------- kernel 3: RoPE apply + head split + bf16 hi/lo emit ----------------
__global__ void rope_apply_kernel() {
    int i = blockIdx.x * blockDim.x + threadIdx.x;
    if (i >= QS) return;
    int d = i & 63;
    int s = (i >> 6) & 511;
    int bh = i >> 15;
    int h = bh & 15;
    int b = bh >> 4;

    size_t base = (size_t)(b * SEQ + s) * QKV_N + h * D_HEAD + d;
    float qr = g_qkv_r[base];
    float qi = g_qkv_i[base];
    float kr = g_qkv_r[base + D_MODEL];
    float ki = g_qkv_i[base + D_MODEL];
    float vr = g_qkv_r[base + 2 * D_MODEL];
    float vi = g_qkv_i[base + 2 * D_MODEL];

    float cs = g_rope_cos[s * D_HEAD + d];
    float sn = g_rope_sin[s * D_HEAD + d];

    float Qr = qr * cs - qi * sn;
    float Qi = qr * sn + qi * cs;
    float Kr = kr * cs - ki * sn;
    float Ki = kr * sn + ki * cs;

    __nv_bfloat16 H, L;
    bsplit(Qr, H, L); g_QrH[i] = H; g_QrL[i] = L;
    bsplit(Qi, H, L); g_QiH[i] = H; g_QiL[i] = L;
    bsplit(Kr, H, L); g_KrH[i] = H; g_KrL[i] = L;
    bsplit(Ki, H, L); g_KiH[i] = H; g_KiL[i] = L;

    size_t j = (size_t)bh * (64 * SEQ) + (size_t)d * SEQ + s;   // transposed [bh][d][s]
    bsplit(vr, H, L); g_VrH[j] = H; g_VrL[j] = L;
    bsplit(vi, H, L); g_ViH[j] = H; g_ViL[j] = L;
}

// ---------------- kernel 4: tensor-core flash attention (complex) ----------------
// CTA: 128 queries x one (b,h). 8 warps, warp w owns rows w*16..w*16+15.
// Epilogue emits bf16 hi/lo (+sum) splits directly for the output projection.
#define AP    144
#define QCOMP (128 * AP)
#define KCOMP (64 * AP)
#define SQ_BYTES (4 * QCOMP)
#define ASTAGE   (8 * KCOMP)
#define A_SMEM   (SQ_BYTES + 2 * ASTAGE)  // 221184

__global__ __launch_bounds__(256, 1) void attn_tc_kernel() {
    extern __shared__ __align__(128) char smem[];
    const uint32_t sb = smem_u32(smem);
    const int tid = threadIdx.x;
    const int lane = tid & 31;
    const int w = tid >> 5;
    const int grp = lane >> 2;
    const int tq = lane & 3;
    const int q0 = blockIdx.x * 128;
    const int bh = blockIdx.y;
    const float scale = 0.125f;

    const __nv_bfloat16* gQ[4] = {g_QrH, g_QrL, g_QiH, g_QiL};
    const __nv_bfloat16* gK[4] = {g_KrH, g_KrL, g_KiH, g_KiL};
    const __nv_bfloat16* gV[4] = {g_VrH, g_VrL, g_ViH, g_ViL};
    const size_t hbQ = (size_t)bh * (SEQ * 64);

    {
#pragma unroll
        for (int it = 0; it < 16; it++) {
            int idx = tid + it * 256;
            int comp = idx >> 10;
            int rem = idx & 1023;
            int row = rem >> 3;
            int ch = rem & 7;
            cp_async16(sb + comp * QCOMP + row * AP + ch * 16,
                       gQ[comp] + hbQ + (size_t)(q0 + row) * 64 + ch * 8);
        }
    }
    auto load_stage = [&](int st, int c0) {
        uint32_t base = sb + SQ_BYTES + st * ASTAGE;
#pragma unroll
        for (int it = 0; it < 16; it++) {
            int idx = tid + it * 256;
            int comp = idx >> 9;
            int rem = idx & 511;
            int row = rem >> 3;
            int ch = rem & 7;
            const __nv_bfloat16* src;
            if (comp < 4) src = gK[comp] + hbQ + (size_t)(c0 + row) * 64 + ch * 8;
            else          src = gV[comp - 4] + hbQ + (size_t)row * SEQ + c0 + ch * 8;
            cp_async16(base + comp * KCOMP + row * AP + ch * 16, src);
        }
        cp_commit();
    };
    load_stage(0, 0);

    float or_[8][4], oi_[8][4];
#pragma unroll
    for (int nt = 0; nt < 8; nt++)
#pragma unroll
        for (int q = 0; q < 4; q++) { or_[nt][q] = 0.f; oi_[nt][q] = 0.f; }
    float m0 = -1e30f, m1 = -1e30f, l0 = 0.f, l1 = 0.f;

    for (int kc = 0; kc < 8; kc++) {
        if (kc < 7) { load_stage((kc + 1) & 1, (kc + 1) * 64); cp_wait<1>(); }
        else        { cp_wait<0>(); }
        __syncthreads();
        const uint32_t stg = sb + SQ_BYTES + (kc & 1) * ASTAGE;

        float sre[8][4], sim[8][4];
#pragma unroll
        for (int nt = 0; nt < 8; nt++)
#pragma unroll
            for (int q = 0; q < 4; q++) { sre[nt][q] = 0.f; sim[nt][q] = 0.f; }

        const uint32_t krow = ((lane >> 4) & 1) * 8 + (lane & 7);
        const uint32_t koff = ((lane >> 3) & 1) * 16;

#pragma unroll
        for (int ks = 0; ks < 4; ks++) {
            uint32_t qa = sb + (uint32_t)(w * 16 + (lane & 15)) * AP + ks * 32 + (lane >> 4) * 16;
            uint32_t qrH[4], qrL[4], qiH[4], qiL[4];
            ldsm_x4(qrH, qa + 0 * QCOMP);
            ldsm_x4(qrL, qa + 1 * QCOMP);
            ldsm_x4(qiH, qa + 2 * QCOMP);
            ldsm_x4(qiL, qa + 3 * QCOMP);
#pragma unroll
            for (int nt16 = 0; nt16 < 4; nt16++) {
                uint32_t kb = stg + (uint32_t)(nt16 * 16 + krow) * AP + ks * 32 + koff;
                uint32_t krH[4], krL[4], kiH[4], kiL[4];
                ldsm_x4(krH, kb + 0 * KCOMP);
                ldsm_x4(krL, kb + 1 * KCOMP);
                ldsm_x4(kiH, kb + 2 * KCOMP);
                ldsm_x4(kiL, kb + 3 * KCOMP);
#pragma unroll
                for (int hf = 0; hf < 2; hf++) {
                    int nt = nt16 * 2 + hf;
                    const uint32_t* bRH = krH + hf * 2;
                    const uint32_t* bRL = krL + hf * 2;
                    const uint32_t* bIH = kiH + hf * 2;
                    const uint32_t* bIL = kiL + hf * 2;
                    uint32_t nIH[2] = {bIH[0] ^ SGNX2, bIH[1] ^ SGNX2};
                    uint32_t nIL[2] = {bIL[0] ^ SGNX2, bIL[1] ^ SGNX2};
                    mma_bf16(sre[nt], qrH, bRH);
                    mma_bf16(sre[nt], qrH, bRL);
                    mma_bf16(sre[nt], qrL, bRH);
                    mma_bf16(sre[nt], qiH, bIH);
                    mma_bf16(sre[nt], qiH, bIL);
                    mma_bf16(sre[nt], qiL, bIH);
                    mma_bf16(sim[nt], qiH, bRH);
                    mma_bf16(sim[nt], qiH, bRL);
                    mma_bf16(sim[nt], qiL, bRH);
                    mma_bf16(sim[nt], qrH, nIH);
                    mma_bf16(sim[nt], qrH, nIL);
                    mma_bf16(sim[nt], qrL, nIH);
                }
            }
        }

        float cx0 = -1e30f, cx1 = -1e30f;
#pragma unroll
        for (int nt = 0; nt < 8; nt++) {
#pragma unroll
            for (int q = 0; q < 4; q++) { sre[nt][q] *= scale; sim[nt][q] *= scale; }
            cx0 = fmaxf(cx0, fmaxf(sre[nt][0], sre[nt][1]));
            cx1 = fmaxf(cx1, fmaxf(sre[nt][2], sre[nt][3]));
        }
        cx0 = fmaxf(cx0, __shfl_xor_sync(0xffffffffu, cx0, 1));
        cx0 = fmaxf(cx0, __shfl_xor_sync(0xffffffffu, cx0, 2));
        cx1 = fmaxf(cx1, __shfl_xor_sync(0xffffffffu, cx1, 1));
        cx1 = fmaxf(cx1, __shfl_xor_sync(0xffffffffu, cx1, 2));

        float nm0 = fmaxf(m0, cx0), nm1 = fmaxf(m1, cx1);
        float al0 = __expf(m0 - nm0), al1 = __expf(m1 - nm1);
        m0 = nm0; m1 = nm1;

        float rs0 = 0.f, rs1 = 0.f;
#pragma unroll
        for (int nt = 0; nt < 8; nt++) {
            float p0 = __expf(sre[nt][0] - nm0);
            float p1 = __expf(sre[nt][1] - nm0);
            float p2 = __expf(sre[nt][2] - nm1);
            float p3 = __expf(sre[nt][3] - nm1);
            rs0 += p0 + p1; rs1 += p2 + p3;
            float sn, cs;
            __sincosf(sim[nt][0], &sn, &cs); sre[nt][0] = p0 * cs; sim[nt][0] = p0 * sn;
            __sincosf(sim[nt][1], &sn, &cs); sre[nt][1] = p1 * cs; sim[nt][1] = p1 * sn;
            __sincosf(sim[nt][2], &sn, &cs); sre[nt][2] = p2 * cs; sim[nt][2] = p2 * sn;
            __sincosf(sim[nt][3], &sn, &cs); sre[nt][3] = p3 * cs; sim[nt][3] = p3 * sn;
        }
        rs0 += __shfl_xor_sync(0xffffffffu, rs0, 1);
        rs0 += __shfl_xor_sync(0xffffffffu, rs0, 2);
        rs1 += __shfl_xor_sync(0xffffffffu, rs1, 1);
        rs1 += __shfl_xor_sync(0xffffffffu, rs1, 2);
        l0 = l0 * al0 + rs0;
        l1 = l1 * al1 + rs1;
#pragma unroll
        for (int nt = 0; nt < 8; nt++) {
            or_[nt][0] *= al0; or_[nt][1] *= al0; or_[nt][2] *= al1; or_[nt][3] *= al1;
            oi_[nt][0] *= al0; oi_[nt][1] *= al0; oi_[nt][2] *= al1; oi_[nt][3] *= al1;
        }

        uint32_t wcH[4][4], wcL[4][4], wsH[4][4], wsL[4][4];
#pragma unroll
        for (int t = 0; t < 4; t++)
#pragma unroll
            for (int r = 0; r < 4; r++) {
                int nt = 2 * t + (r >> 1);
                int e = (r & 1) * 2;
                __nv_bfloat16 h0, lo0, h1, lo1;
                bsplit(sre[nt][e], h0, lo0); bsplit(sre[nt][e + 1], h1, lo1);
                wcH[t][r] = packbf2(h0, h1); wcL[t][r] = packbf2(lo0, lo1);
                bsplit(sim[nt][e], h0, lo0); bsplit(sim[nt][e + 1], h1, lo1);
                wsH[t][r] = packbf2(h0, h1); wsL[t][r] = packbf2(lo0, lo1);
            }

#pragma unroll
        for (int ks = 0; ks < 4; ks++) {
#pragma unroll
            for (int nt16 = 0; nt16 < 4; nt16++) {
                uint32_t vb = stg + (uint32_t)(nt16 * 16 + krow) * AP + ks * 32 + koff;
                uint32_t vrH[4], vrL[4], viH[4], viL[4];
                ldsm_x4(vrH, vb + 4 * KCOMP);
                ldsm_x4(vrL, vb + 5 * KCOMP);
                ldsm_x4(viH, vb + 6 * KCOMP);
                ldsm_x4(viL, vb + 7 * KCOMP);
#pragma unroll
                for (int hf = 0; hf < 2; hf++) {
                    int nt = nt16 * 2 + hf;
                    const uint32_t* bRH = vrH + hf * 2;
                    const uint32_t* bRL = vrL + hf * 2;
                    const uint32_t* bIH = viH + hf * 2;
                    const uint32_t* bIL = viL + hf * 2;
                    uint32_t nIH[2] = {bIH[0] ^ SGNX2, bIH[1] ^ SGNX2};
                    uint32_t nIL[2] = {bIL[0] ^ SGNX2, bIL[1] ^ SGNX2};
                    mma_bf16(or_[nt], wcH[ks], bRH);
                    mma_bf16(or_[nt], wcH[ks], bRL);
                    mma_bf16(or_[nt], wcL[ks], bRH);
                    mma_bf16(or_[nt], wsH[ks], nIH);
                    mma_bf16(or_[nt], wsH[ks], nIL);
                    mma_bf16(or_[nt], wsL[ks], nIH);
                    mma_bf16(oi_[nt], wcH[ks], bIH);
                    mma_bf16(oi_[nt], wcH[ks], bIL);
                    mma_bf16(oi_[nt], wcL[ks], bIH);
                    mma_bf16(oi_[nt], wsH[ks], bRH);
                    mma_bf16(oi_[nt], wsH[ks], bRL);
                    mma_bf16(oi_[nt], wsL[ks], bRH);
                }
            }
        }
        __syncthreads();
    }

    // ---- epilogue: emit bf16 hi/lo (+sum) splits directly ----
    int b = bh >> 4;
    int h = bh & 15;
    float inv0 = 1.0f / l0, inv1 = 1.0f / l1;
    int qr0 = q0 + w * 16 + grp;
#pragma unroll
    for (int nt = 0; nt < 8; nt++) {
        int col = h * 64 + nt * 8 + tq * 2;
        size_t r0 = (size_t)(b * SEQ + qr0) * D_MODEL + col;
        size_t r1 = (size_t)(b * SEQ + qr0 + 8) * D_MODEL + col;
#pragma unroll
        for (int half = 0; half < 2; half++) {
            size_t rr = half ? r1 : r0;
            float inv = half ? inv1 : inv0;
            float ar0 = or_[nt][half * 2 + 0] * inv;
            float ar1 = or_[nt][half * 2 + 1] * inv;
            float ai0 = oi_[nt][half * 2 + 0] * inv;
            float ai1 = oi_[nt][half * 2 + 1] * inv;
            __nv_bfloat16 h0, lo0, h1, lo1;
            bsplit(ar0, h0, lo0); bsplit(ar1, h1, lo1);
            *(uint32_t*)(g_arH + rr) = packbf2(h0, h1);
            *(uint32_t*)(g_arL + rr) = packbf2(lo0, lo1);
            bsplit(ai0, h0, lo0); bsplit(ai1, h1, lo1);
            *(uint32_t*)(g_aiH + rr) = packbf2(h0, h1);
            *(uint32_t*)(g_aiL + rr) = packbf2(lo0, lo1);
            bsplit(ar0 + ai0, h0, lo0); bsplit(ar1 + ai1, h1, lo1);
            *(uint32_t*)(g_asH + rr) = packbf2(h0, h1);
            *(uint32_t*)(g_asL + rr) = packbf2(lo0, lo1);
        }
    }
}

// ---------------- launch ----------------
extern "C" void kernel_launch(void* const* d_in, const int* in_sizes, int n_in,
                              void* d_out, int out_size) {
    (void)in_sizes; (void)n_in; (void)out_size;
    const float* x_re    = (const float*)d_in[0];
    const float* x_im    = (const float*)d_in[1];
    const float* wqkv_re = (const float*)d_in[2];
    const float* wqkv_im = (const float*)d_in[3];
    const float* wo_re   = (const float*)d_in[4];
    const float* wo_im   = (const float*)d_in[5];
    float* out = (float*)d_out;

    float *p_qkv_r, *p_qkv_i;
    cudaGetSymbolAddress((void**)&p_qkv_r, g_qkv_r);
    cudaGetSymbolAddress((void**)&p_qkv_i, g_qkv_i);

    __nv_bfloat16 *xrH, *xrL, *xiH, *xiL, *xsH, *xsL;
    __nv_bfloat16 *wqrH, *wqrL, *wqiH, *wqiL, *wqsH, *wqsL;
    __nv_bfloat16 *worH, *worL, *woiH, *woiL, *wosH, *wosL;
    __nv_bfloat16 *arH, *arL, *aiH, *aiL, *asH, *asL;
    cudaGetSymbolAddress((void**)&xrH, g_xrH);   cudaGetSymbolAddress((void**)&xrL, g_xrL);
    cudaGetSymbolAddress((void**)&xiH, g_xiH);   cudaGetSymbolAddress((void**)&xiL, g_xiL);
    cudaGetSymbolAddress((void**)&xsH, g_xsH);   cudaGetSymbolAddress((void**)&xsL, g_xsL);
    cudaGetSymbolAddress((void**)&wqrH, g_wqrH); cudaGetSymbolAddress((void**)&wqrL, g_wqrL);
    cudaGetSymbolAddress((void**)&wqiH, g_wqiH); cudaGetSymbolAddress((void**)&wqiL, g_wqiL);
    cudaGetSymbolAddress((void**)&wqsH, g_wqsH); cudaGetSymbolAddress((void**)&wqsL, g_wqsL);
    cudaGetSymbolAddress((void**)&worH, g_worH); cudaGetSymbolAddress((void**)&worL, g_worL);
    cudaGetSymbolAddress((void**)&woiH, g_woiH); cudaGetSymbolAddress((void**)&woiL, g_woiL);
    cudaGetSymbolAddress((void**)&wosH, g_wosH); cudaGetSymbolAddress((void**)&wosL, g_wosL);
    cudaGetSymbolAddress((void**)&arH, g_arH);   cudaGetSymbolAddress((void**)&arL, g_arL);
    cudaGetSymbolAddress((void**)&aiH, g_aiH);   cudaGetSymbolAddress((void**)&aiL, g_aiL);
    cudaGetSymbolAddress((void**)&asH, g_asH);   cudaGetSymbolAddress((void**)&asL, g_asL);

    cudaFuncSetAttribute(cgemm_tc_kernel,
                         cudaFuncAttributeMaxDynamicSharedMemorySize, G_SMEM);
    cudaFuncSetAttribute(attn_tc_kernel,
                         cudaFuncAttributeMaxDynamicSharedMemorySize, A_SMEM);

    // 1. rope table
    rope_table_kernel<<<(SEQ * D_HEAD + 255) / 256, 256>>>();

    // 2. complex splits (re, im, re+im) of inputs + weights
    split2_kernel<<<(XN / 4 + 255) / 256, 256>>>(x_re, x_im, xrH, xrL, xiH, xiL, xsH, xsL, XN / 4);
    split2_kernel<<<(WQN / 4 + 255) / 256, 256>>>(wqkv_re, wqkv_im, wqrH, wqrL, wqiH, wqiL, wqsH, wqsL, WQN / 4);
    split2_kernel<<<(WON / 4 + 255) / 256, 256>>>(wo_re, wo_im, worH, worL, woiH, woiL, wosH, wosL, WON / 4);

    // 3. QKV projection (Karatsuba tensor-core GEMM)
    {
        dim3 grid(QKV_N / GBN, M_TOK / GBM);
        cgemm_tc_kernel<<<grid, 256, G_SMEM>>>(
            xrH, xrL, xiH, xiL, xsH, xsL,
            wqrH, wqrL, wqiH, wqiL, wqsH, wqsL,
            p_qkv_r, p_qkv_i, QKV_N, D_MODEL);
    }

    // 4. rope apply + head split + bf16 emit
    rope_apply_kernel<<<(QS + 255) / 256, 256>>>();

    // 5. tensor-core flash attention (emits output splits directly)
    {
        dim3 grid(SEQ / 128, BHN);
        attn_tc_kernel<<<grid, 256, A_SMEM>>>();
    }

    // 6. output projection (Karatsuba tensor-core GEMM) -> d_out
    {
        dim3 grid(D_MODEL / GBN, M_TOK / GBM);
        cgemm_tc_kernel<<<grid, 256, G_SMEM>>>(
            arH, arL, aiH, aiL, asH, asL,
            worH, worL, woiH, woiL, wosH, wosL,
            out, out + (size_t)M_TOK * D_MODEL, D_MODEL, D_MODEL);
    }
}

// round 10
// speedup vs baseline: 1.0860x; 1.0860x over previous
#include <cuda_runtime.h>
#include <cuda_bf16.h>
#include <math.h>
#include <stdint.h>

// Problem constants
#define D_MODEL 1024
#define N_HEADS 16
#define D_HEAD  64
#define BATCH   4
#define SEQ     512
#define M_TOK   (BATCH * SEQ)       // 2048
#define QKV_N   (3 * D_MODEL)       // 3072
#define BHN     (BATCH * N_HEADS)   // 64
#define QS      (BHN * SEQ * D_HEAD) // 2097152

// ---------------- device scratch (no runtime allocation allowed) ----------------
__device__ float g_rope_cos[SEQ * D_HEAD];
__device__ float g_rope_sin[SEQ * D_HEAD];

// bf16 hi/lo splits for projection GEMMs
#define XN   (M_TOK * D_MODEL)      // 2097152
#define WQN  (QKV_N * D_MODEL)      // 3145728
#define WON  (D_MODEL * D_MODEL)    // 1048576
__device__ __nv_bfloat16 g_xrH[XN],  g_xrL[XN],  g_xiH[XN],  g_xiL[XN];
__device__ __nv_bfloat16 g_wqrH[WQN], g_wqrL[WQN], g_wqiH[WQN], g_wqiL[WQN];
__device__ __nv_bfloat16 g_worH[WON], g_worL[WON], g_woiH[WON], g_woiL[WON];
__device__ __nv_bfloat16 g_arH[XN],  g_arL[XN],  g_aiH[XN],  g_aiL[XN];

// bf16 hi/lo splits for attention (written by fused QKV-GEMM epilogue)
// Q, K: [bh][s][d] token-major.  V: [bh][d][s] dim-major (transposed, B-frag ready).
__device__ __nv_bfloat16 g_QrH[QS], g_QrL[QS], g_QiH[QS], g_QiL[QS];
__device__ __nv_bfloat16 g_KrH[QS], g_KrL[QS], g_KiH[QS], g_KiL[QS];
__device__ __nv_bfloat16 g_VrH[QS], g_VrL[QS], g_ViH[QS], g_ViL[QS];

// ================= PTX helpers (baseline ISA only — no tcgen05) =================
__device__ __forceinline__ uint32_t smem_u32(const void* p) {
    uint32_t a;
    asm("{ .reg .u64 t; cvta.to.shared.u64 t, %1; cvt.u32.u64 %0, t; }" : "=r"(a) : "l"(p));
    return a;
}
__device__ __forceinline__ void cp_async16(uint32_t dst, const void* src) {
    asm volatile("cp.async.cg.shared.global [%0], [%1], 16;" :: "r"(dst), "l"(src));
}
__device__ __forceinline__ void cp_commit() {
    asm volatile("cp.async.commit_group;" ::: "memory");
}
template <int N> __device__ __forceinline__ void cp_wait() {
    asm volatile("cp.async.wait_group %0;" :: "n"(N) : "memory");
}
__device__ __forceinline__ void ldsm_x4(uint32_t* r, uint32_t a) {
    asm volatile("ldmatrix.sync.aligned.m8n8.x4.shared.b16 {%0,%1,%2,%3}, [%4];"
                 : "=r"(r[0]), "=r"(r[1]), "=r"(r[2]), "=r"(r[3]) : "r"(a));
}
// D += A(16x16 bf16, row) * B(16x8 bf16, col), fp32 accumulate
__device__ __forceinline__ void mma_bf16(float* c, const uint32_t* a, const uint32_t* b) {
    asm volatile(
        "mma.sync.aligned.m16n8k16.row.col.f32.bf16.bf16.f32 "
        "{%0,%1,%2,%3}, {%4,%5,%6,%7}, {%8,%9}, {%0,%1,%2,%3};"
        : "+f"(c[0]), "+f"(c[1]), "+f"(c[2]), "+f"(c[3])
        : "r"(a[0]), "r"(a[1]), "r"(a[2]), "r"(a[3]), "r"(b[0]), "r"(b[1]));
}
__device__ __forceinline__ void bsplit(float v, __nv_bfloat16& h, __nv_bfloat16& l) {
    h = __float2bfloat16_rn(v);
    l = __float2bfloat16_rn(v - __bfloat162float(h));
}
__device__ __forceinline__ uint32_t packbf2(__nv_bfloat16 a, __nv_bfloat16 b) {
    __nv_bfloat162 t{a, b};
    return *reinterpret_cast<uint32_t*>(&t);
}
#define SGNX2 0x80008000u

// ---------------- kernel 1: RoPE rotor table ----------------
__global__ void rope_table_kernel() {
    int i = blockIdx.x * blockDim.x + threadIdx.x;
    if (i >= SEQ * D_HEAD) return;
    int s = i / D_HEAD;
    int d = i % D_HEAD;
    float inv_freq = powf(10000.0f, -(float)d / (float)D_HEAD);
    float ang = (float)s * inv_freq;
    float sn, cs;
    sincosf(ang, &sn, &cs);
    g_rope_cos[i] = cs;
    g_rope_sin[i] = sn;
}

// ---------------- kernel 1b: complex hi/lo split (re, im) ----------------
__global__ void split_cx_kernel(const float* __restrict__ re, const float* __restrict__ im,
                                __nv_bfloat16* __restrict__ rH, __nv_bfloat16* __restrict__ rL,
                                __nv_bfloat16* __restrict__ iH, __nv_bfloat16* __restrict__ iL,
                                int n4) {
    int i = blockIdx.x * blockDim.x + threadIdx.x;
    if (i >= n4) return;
    float4 vr = ((const float4*)re)[i];
    float4 vi = ((const float4*)im)[i];
    __nv_bfloat16 h0, h1, h2, h3, l0, l1, l2, l3;

    bsplit(vr.x, h0, l0); bsplit(vr.y, h1, l1); bsplit(vr.z, h2, l2); bsplit(vr.w, h3, l3);
    ((uint32_t*)rH)[i * 2 + 0] = packbf2(h0, h1);
    ((uint32_t*)rH)[i * 2 + 1] = packbf2(h2, h3);
    ((uint32_t*)rL)[i * 2 + 0] = packbf2(l0, l1);
    ((uint32_t*)rL)[i * 2 + 1] = packbf2(l2, l3);

    bsplit(vi.x, h0, l0); bsplit(vi.y, h1, l1); bsplit(vi.z, h2, l2); bsplit(vi.w, h3, l3);
    ((uint32_t*)iH)[i * 2 + 0] = packbf2(h0, h1);
    ((uint32_t*)iH)[i * 2 + 1] = packbf2(h2, h3);
    ((uint32_t*)iL)[i * 2 + 0] = packbf2(l0, l1);
    ((uint32_t*)iL)[i * 2 + 1] = packbf2(l2, l3);
}

// ---------------- kernel 2: mma.sync complex GEMM  C = A @ B^T ----------------
// Direct form (12 HMMA per micro-tile): Cre = ArBr - AiBi (neg-Bi frags), Cim = ArBi + AiBr.
// CTA tile 128x64, K-stage 32, 3-stage cp.async pipeline, 8 warps (4m x 2n).
// B fragments loaded with ldsm_x4 (2 n8-tiles per load).
// FUSE_ROPE epilogue: applies RoPE + head-split + bf16 hi/lo emit for Q/K/V.
#define GBM 128
#define GBN 64
#define GBK 32
#define GPITCHB 80
#define A_COMP_B (GBM * GPITCHB)              // 10240
#define B_COMP_B (GBN * GPITCHB)              // 5120
#define STAGE_B  (4 * A_COMP_B + 4 * B_COMP_B) // 61440
#define G_SMEM   (3 * STAGE_B)                 // 184320

template <bool FUSE_ROPE>
__global__ __launch_bounds__(256, 1) void cgemm_tc_kernel(
    const __nv_bfloat16* __restrict__ ArH, const __nv_bfloat16* __restrict__ ArL,
    const __nv_bfloat16* __restrict__ AiH, const __nv_bfloat16* __restrict__ AiL,
    const __nv_bfloat16* __restrict__ BrH, const __nv_bfloat16* __restrict__ BrL,
    const __nv_bfloat16* __restrict__ BiH, const __nv_bfloat16* __restrict__ BiL,
    float* __restrict__ Cre, float* __restrict__ Cim,
    int N, int K)
{
    extern __shared__ __align__(128) char smem[];
    const uint32_t sb = smem_u32(smem);
    const int tid = threadIdx.x;
    const int lane = tid & 31;
    const int wid = tid >> 5;
    const int wm = wid & 3;
    const int wn = wid >> 2;
    const int m0 = blockIdx.y * GBM;
    const int n0 = blockIdx.x * GBN;

    const __nv_bfloat16* Ap[4] = {ArH, ArL, AiH, AiL};
    const __nv_bfloat16* Bp[4] = {BrH, BrL, BiH, BiL};

    auto load_stage = [&](int st, int k0) {
        uint32_t base = sb + st * STAGE_B;
#pragma unroll
        for (int i = 0; i < 8; i++) {
            int idx = tid + i * 256;
            int comp = idx >> 9;
            int rem = idx & 511;
            int row = rem >> 2;
            int ch = rem & 3;
            cp_async16(base + comp * A_COMP_B + row * GPITCHB + ch * 16,
                       Ap[comp] + (size_t)(m0 + row) * K + k0 + ch * 8);
        }
        uint32_t bbase = base + 4 * A_COMP_B;
#pragma unroll
        for (int i = 0; i < 4; i++) {
            int idx = tid + i * 256;
            int comp = idx >> 8;
            int rem = idx & 255;
            int row = rem >> 2;
            int ch = rem & 3;
            cp_async16(bbase + comp * B_COMP_B + row * GPITCHB + ch * 16,
                       Bp[comp] + (size_t)(n0 + row) * K + k0 + ch * 8);
        }
        cp_commit();
    };

    float cre[2][4][4];
    float cim[2][4][4];
#pragma unroll
    for (int mt = 0; mt < 2; mt++)
#pragma unroll
        for (int nt = 0; nt < 4; nt++)
#pragma unroll
            for (int q = 0; q < 4; q++) { cre[mt][nt][q] = 0.f; cim[mt][nt][q] = 0.f; }

    const int NC = K / GBK;
    load_stage(0, 0);
    load_stage(1, GBK);

    const uint32_t krow = ((lane >> 4) & 1) * 8 + (lane & 7);
    const uint32_t koff = ((lane >> 3) & 1) * 16;

    for (int c = 0; c < NC; c++) {
        if (c + 2 < NC) { load_stage((c + 2) % 3, (c + 2) * GBK); cp_wait<2>(); }
        else if (c + 1 < NC) cp_wait<1>();
        else cp_wait<0>();
        __syncthreads();

        const uint32_t abase = sb + (c % 3) * STAGE_B;
        const uint32_t bbase = abase + 4 * A_COMP_B;

#pragma unroll
        for (int ks = 0; ks < 2; ks++) {
            uint32_t af[4][2][4];
#pragma unroll
            for (int comp = 0; comp < 4; comp++)
#pragma unroll
                for (int mt = 0; mt < 2; mt++) {
                    uint32_t addr = abase + comp * A_COMP_B
                        + (uint32_t)(wm * 32 + mt * 16 + (lane & 15)) * GPITCHB
                        + ks * 32 + (lane >> 4) * 16;
                    ldsm_x4(af[comp][mt], addr);
                }
            uint32_t bfr[4][2][4];        // [comp][nt16][4 regs = 2 b-frags]
#pragma unroll
            for (int comp = 0; comp < 4; comp++)
#pragma unroll
                for (int nt16 = 0; nt16 < 2; nt16++) {
                    uint32_t addr = bbase + comp * B_COMP_B
                        + (uint32_t)(wn * 32 + nt16 * 16 + krow) * GPITCHB
                        + ks * 32 + koff;
                    ldsm_x4(bfr[comp][nt16], addr);
                }
#pragma unroll
            for (int nt16 = 0; nt16 < 2; nt16++)
#pragma unroll
                for (int hf = 0; hf < 2; hf++) {
                    int nt = nt16 * 2 + hf;
                    const uint32_t* bRH = bfr[0][nt16] + hf * 2;
                    const uint32_t* bRL = bfr[1][nt16] + hf * 2;
                    const uint32_t* bIH = bfr[2][nt16] + hf * 2;
                    const uint32_t* bIL = bfr[3][nt16] + hf * 2;
                    uint32_t nIH[2] = {bIH[0] ^ SGNX2, bIH[1] ^ SGNX2};
                    uint32_t nIL[2] = {bIL[0] ^ SGNX2, bIL[1] ^ SGNX2};
#pragma unroll
                    for (int mt = 0; mt < 2; mt++) {
                        float* cr = cre[mt][nt];
                        float* ci = cim[mt][nt];
                        mma_bf16(cr, af[0][mt], bRH);
                        mma_bf16(cr, af[0][mt], bRL);
                        mma_bf16(cr, af[1][mt], bRH);
                        mma_bf16(cr, af[2][mt], nIH);
                        mma_bf16(cr, af[2][mt], nIL);
                        mma_bf16(cr, af[3][mt], nIH);
                        mma_bf16(ci, af[0][mt], bIH);
                        mma_bf16(ci, af[0][mt], bIL);
                        mma_bf16(ci, af[1][mt], bIH);
                        mma_bf16(ci, af[2][mt], bRH);
                        mma_bf16(ci, af[2][mt], bRL);
                        mma_bf16(ci, af[3][mt], bRH);
                    }
                }
        }
        __syncthreads();
    }

    // ---- epilogue ----
#pragma unroll
    for (int mt = 0; mt < 2; mt++) {
        int row0 = m0 + wm * 32 + mt * 16 + (lane >> 2);
#pragma unroll
        for (int nt = 0; nt < 4; nt++) {
            int col = n0 + wn * 32 + nt * 8 + (lane & 3) * 2;
            if (!FUSE_ROPE) {
                *(float2*)(Cre + (size_t)row0 * N + col) = {cre[mt][nt][0], cre[mt][nt][1]};
                *(float2*)(Cre + (size_t)(row0 + 8) * N + col) = {cre[mt][nt][2], cre[mt][nt][3]};
                *(float2*)(Cim + (size_t)row0 * N + col) = {cim[mt][nt][0], cim[mt][nt][1]};
                *(float2*)(Cim + (size_t)(row0 + 8) * N + col) = {cim[mt][nt][2], cim[mt][nt][3]};
            } else {
                int sec = col >> 10;          // 0=Q, 1=K, 2=V
                int hd = col & 1023;
                int h = hd >> 6;
                int d = hd & 63;
#pragma unroll
                for (int half = 0; half < 2; half++) {
                    int tkn = row0 + half * 8;
                    int b = tkn >> 9;
                    int s = tkn & 511;
                    int bh = (b << 4) + h;
                    float re0 = cre[mt][nt][half * 2 + 0];
                    float re1 = cre[mt][nt][half * 2 + 1];
                    float im0 = cim[mt][nt][half * 2 + 0];
                    float im1 = cim[mt][nt][half * 2 + 1];
                    if (sec == 2) {
                        size_t j = (size_t)bh * 32768 + (size_t)d * 512 + s;
                        __nv_bfloat16 H, L;
                        bsplit(re0, H, L); g_VrH[j] = H; g_VrL[j] = L;
                        bsplit(im0, H, L); g_ViH[j] = H; g_ViL[j] = L;
                        bsplit(re1, H, L); g_VrH[j + 512] = H; g_VrL[j + 512] = L;
                        bsplit(im1, H, L); g_ViH[j + 512] = H; g_ViL[j + 512] = L;
                    } else {
                        float2 rc = *(const float2*)(g_rope_cos + s * 64 + d);
                        float2 rs = *(const float2*)(g_rope_sin + s * 64 + d);
                        float ar0 = re0 * rc.x - im0 * rs.x;
                        float ai0 = re0 * rs.x + im0 * rc.x;
                        float ar1 = re1 * rc.y - im1 * rs.y;
                        float ai1 = re1 * rs.y + im1 * rc.y;
                        size_t i = (size_t)bh * 32768 + s * 64 + d;
                        __nv_bfloat16 h0, l0, h1, l1;
                        if (sec == 0) {
                            bsplit(ar0, h0, l0); bsplit(ar1, h1, l1);
                            *(uint32_t*)(g_QrH + i) = packbf2(h0, h1);
                            *(uint32_t*)(g_QrL + i) = packbf2(l0, l1);
                            bsplit(ai0, h0, l0); bsplit(ai1, h1, l1);
                            *(uint32_t*)(g_QiH + i) = packbf2(h0, h1);
                            *(uint32_t*)(g_QiL + i) = packbf2(l0, l1);
                        } else {
                            bsplit(ar0, h0, l0); bsplit(ar1, h1, l1);
                            *(uint32_t*)(g_KrH + i) = packbf2(h0, h1);
                            *(uint32_t*)(g_KrL + i) = packbf2(l0, l1);
                            bsplit(ai0, h0, l0); bsplit(ai1, h1, l1);
                            *(uint32_t*)(g_KiH + i) = packbf2(h0, h1);
                            *(uint32_t*)(g_KiL + i) = packbf2(l0, l1);
                        }
                    }
                }
            }
        }
    }
}

// ---------------- kernel 4: tensor-core flash attention (complex) ----------------
// CTA: 128 queries x one (b,h). 8 warps, warp w owns rows w*16..w*16+15.
// Epilogue emits bf16 hi/lo splits directly for the output projection.
#define AP    144
#define QCOMP (128 * AP)
#define KCOMP (64 * AP)
#define SQ_BYTES (4 * QCOMP)
#define ASTAGE   (8 * KCOMP)
#define A_SMEM   (SQ_BYTES + 2 * ASTAGE)  // 221184

__global__ __launch_bounds__(256, 1) void attn_tc_kernel() {
    extern __shared__ __align__(128) char smem[];
    const uint32_t sb = smem_u32(smem);
    const int tid = threadIdx.x;
    const int lane = tid & 31;
    const int w = tid >> 5;
    const int grp = lane >> 2;
    const int tq = lane & 3;
    const int q0 = blockIdx.x * 128;
    const int bh = blockIdx.y;
    const float scale = 0.125f;

    const __nv_bfloat16* gQ[4] = {g_QrH, g_QrL, g_QiH, g_QiL};
    const __nv_bfloat16* gK[4] = {g_KrH, g_KrL, g_KiH, g_KiL};
    const __nv_bfloat16* gV[4] = {g_VrH, g_VrL, g_ViH, g_ViL};
    const size_t hbQ = (size_t)bh * (SEQ * 64);

    {
#pragma unroll
        for (int it = 0; it < 16; it++) {
            int idx = tid + it * 256;
            int comp = idx >> 10;
            int rem = idx & 1023;
            int row = rem >> 3;
            int ch = rem & 7;
            cp_async16(sb + comp * QCOMP + row * AP + ch * 16,
                       gQ[comp] + hbQ + (size_t)(q0 + row) * 64 + ch * 8);
        }
    }
    auto load_stage = [&](int st, int c0) {
        uint32_t base = sb + SQ_BYTES + st * ASTAGE;
#pragma unroll
        for (int it = 0; it < 16; it++) {
            int idx = tid + it * 256;
            int comp = idx >> 9;
            int rem = idx & 511;
            int row = rem >> 3;
            int ch = rem & 7;
            const __nv_bfloat16* src;
            if (comp < 4) src = gK[comp] + hbQ + (size_t)(c0 + row) * 64 + ch * 8;
            else          src = gV[comp - 4] + hbQ + (size_t)row * SEQ + c0 + ch * 8;
            cp_async16(base + comp * KCOMP + row * AP + ch * 16, src);
        }
        cp_commit();
    };
    load_stage(0, 0);

    float or_[8][4], oi_[8][4];
#pragma unroll
    for (int nt = 0; nt < 8; nt++)
#pragma unroll
        for (int q = 0; q < 4; q++) { or_[nt][q] = 0.f; oi_[nt][q] = 0.f; }
    float m0 = -1e30f, m1 = -1e30f, l0 = 0.f, l1 = 0.f;

    for (int kc = 0; kc < 8; kc++) {
        if (kc < 7) { load_stage((kc + 1) & 1, (kc + 1) * 64); cp_wait<1>(); }
        else        { cp_wait<0>(); }
        __syncthreads();
        const uint32_t stg = sb + SQ_BYTES + (kc & 1) * ASTAGE;

        float sre[8][4], sim[8][4];
#pragma unroll
        for (int nt = 0; nt < 8; nt++)
#pragma unroll
            for (int q = 0; q < 4; q++) { sre[nt][q] = 0.f; sim[nt][q] = 0.f; }

        const uint32_t krow = ((lane >> 4) & 1) * 8 + (lane & 7);
        const uint32_t koff = ((lane >> 3) & 1) * 16;

#pragma unroll
        for (int ks = 0; ks < 4; ks++) {
            uint32_t qa = sb + (uint32_t)(w * 16 + (lane & 15)) * AP + ks * 32 + (lane >> 4) * 16;
            uint32_t qrH[4], qrL[4], qiH[4], qiL[4];
            ldsm_x4(qrH, qa + 0 * QCOMP);
            ldsm_x4(qrL, qa + 1 * QCOMP);
            ldsm_x4(qiH, qa + 2 * QCOMP);
            ldsm_x4(qiL, qa + 3 * QCOMP);
#pragma unroll
            for (int nt16 = 0; nt16 < 4; nt16++) {
                uint32_t kb = stg + (uint32_t)(nt16 * 16 + krow) * AP + ks * 32 + koff;
                uint32_t krH[4], krL[4], kiH[4], kiL[4];
                ldsm_x4(krH, kb + 0 * KCOMP);
                ldsm_x4(krL, kb + 1 * KCOMP);
                ldsm_x4(kiH, kb + 2 * KCOMP);
                ldsm_x4(kiL, kb + 3 * KCOMP);
#pragma unroll
                for (int hf = 0; hf < 2; hf++) {
                    int nt = nt16 * 2 + hf;
                    const uint32_t* bRH = krH + hf * 2;
                    const uint32_t* bRL = krL + hf * 2;
                    const uint32_t* bIH = kiH + hf * 2;
                    const uint32_t* bIL = kiL + hf * 2;
                    uint32_t nIH[2] = {bIH[0] ^ SGNX2, bIH[1] ^ SGNX2};
                    uint32_t nIL[2] = {bIL[0] ^ SGNX2, bIL[1] ^ SGNX2};
                    mma_bf16(sre[nt], qrH, bRH);
                    mma_bf16(sre[nt], qrH, bRL);
                    mma_bf16(sre[nt], qrL, bRH);
                    mma_bf16(sre[nt], qiH, bIH);
                    mma_bf16(sre[nt], qiH, bIL);
                    mma_bf16(sre[nt], qiL, bIH);
                    mma_bf16(sim[nt], qiH, bRH);
                    mma_bf16(sim[nt], qiH, bRL);
                    mma_bf16(sim[nt], qiL, bRH);
                    mma_bf16(sim[nt], qrH, nIH);
                    mma_bf16(sim[nt], qrH, nIL);
                    mma_bf16(sim[nt], qrL, nIH);
                }
            }
        }

        float cx0 = -1e30f, cx1 = -1e30f;
#pragma unroll
        for (int nt = 0; nt < 8; nt++) {
#pragma unroll
            for (int q = 0; q < 4; q++) { sre[nt][q] *= scale; sim[nt][q] *= scale; }
            cx0 = fmaxf(cx0, fmaxf(sre[nt][0], sre[nt][1]));
            cx1 = fmaxf(cx1, fmaxf(sre[nt][2], sre[nt][3]));
        }
        cx0 = fmaxf(cx0, __shfl_xor_sync(0xffffffffu, cx0, 1));
        cx0 = fmaxf(cx0, __shfl_xor_sync(0xffffffffu, cx0, 2));
        cx1 = fmaxf(cx1, __shfl_xor_sync(0xffffffffu, cx1, 1));
        cx1 = fmaxf(cx1, __shfl_xor_sync(0xffffffffu, cx1, 2));

        float nm0 = fmaxf(m0, cx0), nm1 = fmaxf(m1, cx1);
        float al0 = __expf(m0 - nm0), al1 = __expf(m1 - nm1);
        m0 = nm0; m1 = nm1;

        float rs0 = 0.f, rs1 = 0.f;
#pragma unroll
        for (int nt = 0; nt < 8; nt++) {
            float p0 = __expf(sre[nt][0] - nm0);
            float p1 = __expf(sre[nt][1] - nm0);
            float p2 = __expf(sre[nt][2] - nm1);
            float p3 = __expf(sre[nt][3] - nm1);
            rs0 += p0 + p1; rs1 += p2 + p3;
            float sn, cs;
            __sincosf(sim[nt][0], &sn, &cs); sre[nt][0] = p0 * cs; sim[nt][0] = p0 * sn;
            __sincosf(sim[nt][1], &sn, &cs); sre[nt][1] = p1 * cs; sim[nt][1] = p1 * sn;
            __sincosf(sim[nt][2], &sn, &cs); sre[nt][2] = p2 * cs; sim[nt][2] = p2 * sn;
            __sincosf(sim[nt][3], &sn, &cs); sre[nt][3] = p3 * cs; sim[nt][3] = p3 * sn;
        }
        rs0 += __shfl_xor_sync(0xffffffffu, rs0, 1);
        rs0 += __shfl_xor_sync(0xffffffffu, rs0, 2);
        rs1 += __shfl_xor_sync(0xffffffffu, rs1, 1);
        rs1 += __shfl_xor_sync(0xffffffffu, rs1, 2);
        l0 = l0 * al0 + rs0;
        l1 = l1 * al1 + rs1;
#pragma unroll
        for (int nt = 0; nt < 8; nt++) {
            or_[nt][0] *= al0; or_[nt][1] *= al0; or_[nt][2] *= al1; or_[nt][3] *= al1;
            oi_[nt][0] *= al0; oi_[nt][1] *= al0; oi_[nt][2] *= al1; oi_[nt][3] *= al1;
        }

        uint32_t wcH[4][4], wcL[4][4], wsH[4][4], wsL[4][4];
#pragma unroll
        for (int t = 0; t < 4; t++)
#pragma unroll
            for (int r = 0; r < 4; r++) {
                int nt = 2 * t + (r >> 1);
                int e = (r & 1) * 2;
                __nv_bfloat16 h0, lo0, h1, lo1;
                bsplit(sre[nt][e], h0, lo0); bsplit(sre[nt][e + 1], h1, lo1);
                wcH[t][r] = packbf2(h0, h1); wcL[t][r] = packbf2(lo0, lo1);
                bsplit(sim[nt][e], h0, lo0); bsplit(sim[nt][e + 1], h1, lo1);
                wsH[t][r] = packbf2(h0, h1); wsL[t][r] = packbf2(lo0, lo1);
            }

#pragma unroll
        for (int ks = 0; ks < 4; ks++) {
#pragma unroll
            for (int nt16 = 0; nt16 < 4; nt16++) {
                uint32_t vb = stg + (uint32_t)(nt16 * 16 + krow) * AP + ks * 32 + koff;
                uint32_t vrH[4], vrL[4], viH[4], viL[4];
                ldsm_x4(vrH, vb + 4 * KCOMP);
                ldsm_x4(vrL, vb + 5 * KCOMP);
                ldsm_x4(viH, vb + 6 * KCOMP);
                ldsm_x4(viL, vb + 7 * KCOMP);
#pragma unroll
                for (int hf = 0; hf < 2; hf++) {
                    int nt = nt16 * 2 + hf;
                    const uint32_t* bRH = vrH + hf * 2;
                    const uint32_t* bRL = vrL + hf * 2;
                    const uint32_t* bIH = viH + hf * 2;
                    const uint32_t* bIL = viL + hf * 2;
                    uint32_t nIH[2] = {bIH[0] ^ SGNX2, bIH[1] ^ SGNX2};
                    uint32_t nIL[2] = {bIL[0] ^ SGNX2, bIL[1] ^ SGNX2};
                    mma_bf16(or_[nt], wcH[ks], bRH);
                    mma_bf16(or_[nt], wcH[ks], bRL);
                    mma_bf16(or_[nt], wcL[ks], bRH);
                    mma_bf16(or_[nt], wsH[ks], nIH);
                    mma_bf16(or_[nt], wsH[ks], nIL);
                    mma_bf16(or_[nt], wsL[ks], nIH);
                    mma_bf16(oi_[nt], wcH[ks], bIH);
                    mma_bf16(oi_[nt], wcH[ks], bIL);
                    mma_bf16(oi_[nt], wcL[ks], bIH);
                    mma_bf16(oi_[nt], wsH[ks], bRH);
                    mma_bf16(oi_[nt], wsH[ks], bRL);
                    mma_bf16(oi_[nt], wsL[ks], bRH);
                }
            }
        }
        __syncthreads();
    }

    // ---- epilogue: emit bf16 hi/lo splits for output projection ----
    int b = bh >> 4;
    int h = bh & 15;
    float inv0 = 1.0f / l0, inv1 = 1.0f / l1;
    int qr0 = q0 + w * 16 + grp;
#pragma unroll
    for (int nt = 0; nt < 8; nt++) {
        int col = h * 64 + nt * 8 + tq * 2;
        size_t r0 = (size_t)(b * SEQ + qr0) * D_MODEL + col;
        size_t r1 = (size_t)(b * SEQ + qr0 + 8) * D_MODEL + col;
#pragma unroll
        for (int half = 0; half < 2; half++) {
            size_t rr = half ? r1 : r0;
            float inv = half ? inv1 : inv0;
            float ar0 = or_[nt][half * 2 + 0] * inv;
            float ar1 = or_[nt][half * 2 + 1] * inv;
            float ai0 = oi_[nt][half * 2 + 0] * inv;
            float ai1 = oi_[nt][half * 2 + 1] * inv;
            __nv_bfloat16 h0, lo0, h1, lo1;
            bsplit(ar0, h0, lo0); bsplit(ar1, h1, lo1);
            *(uint32_t*)(g_arH + rr) = packbf2(h0, h1);
            *(uint32_t*)(g_arL + rr) = packbf2(lo0, lo1);
            bsplit(ai0, h0, lo0); bsplit(ai1, h1, lo1);
            *(uint32_t*)(g_aiH + rr) = packbf2(h0, h1);
            *(uint32_t*)(g_aiL + rr) = packbf2(lo0, lo1);
        }
    }
}

// ---------------- launch ----------------
extern "C" void kernel_launch(void* const* d_in, const int* in_sizes, int n_in,
                              void* d_out, int out_size) {
    (void)in_sizes; (void)n_in; (void)out_size;
    const float* x_re    = (const float*)d_in[0];
    const float* x_im    = (const float*)d_in[1];
    const float* wqkv_re = (const float*)d_in[2];
    const float* wqkv_im = (const float*)d_in[3];
    const float* wo_re   = (const float*)d_in[4];
    const float* wo_im   = (const float*)d_in[5];
    float* out = (float*)d_out;

    __nv_bfloat16 *xrH, *xrL, *xiH, *xiL;
    __nv_bfloat16 *wqrH, *wqrL, *wqiH, *wqiL;
    __nv_bfloat16 *worH, *worL, *woiH, *woiL;
    __nv_bfloat16 *arH, *arL, *aiH, *aiL;
    cudaGetSymbolAddress((void**)&xrH, g_xrH);   cudaGetSymbolAddress((void**)&xrL, g_xrL);
    cudaGetSymbolAddress((void**)&xiH, g_xiH);   cudaGetSymbolAddress((void**)&xiL, g_xiL);
    cudaGetSymbolAddress((void**)&wqrH, g_wqrH); cudaGetSymbolAddress((void**)&wqrL, g_wqrL);
    cudaGetSymbolAddress((void**)&wqiH, g_wqiH); cudaGetSymbolAddress((void**)&wqiL, g_wqiL);
    cudaGetSymbolAddress((void**)&worH, g_worH); cudaGetSymbolAddress((void**)&worL, g_worL);
    cudaGetSymbolAddress((void**)&woiH, g_woiH); cudaGetSymbolAddress((void**)&woiL, g_woiL);
    cudaGetSymbolAddress((void**)&arH, g_arH);   cudaGetSymbolAddress((void**)&arL, g_arL);
    cudaGetSymbolAddress((void**)&aiH, g_aiH);   cudaGetSymbolAddress((void**)&aiL, g_aiL);

    cudaFuncSetAttribute(cgemm_tc_kernel<true>,
                         cudaFuncAttributeMaxDynamicSharedMemorySize, G_SMEM);
    cudaFuncSetAttribute(cgemm_tc_kernel<false>,
                         cudaFuncAttributeMaxDynamicSharedMemorySize, G_SMEM);
    cudaFuncSetAttribute(attn_tc_kernel,
                         cudaFuncAttributeMaxDynamicSharedMemorySize, A_SMEM);

    // 1. rope table
    rope_table_kernel<<<(SEQ * D_HEAD + 255) / 256, 256>>>();

    // 2. complex hi/lo splits of inputs + weights
    split_cx_kernel<<<(XN / 4 + 255) / 256, 256>>>(x_re, x_im, xrH, xrL, xiH, xiL, XN / 4);
    split_cx_kernel<<<(WQN / 4 + 255) / 256, 256>>>(wqkv_re, wqkv_im, wqrH, wqrL, wqiH, wqiL, WQN / 4);
    split_cx_kernel<<<(WON / 4 + 255) / 256, 256>>>(wo_re, wo_im, worH, worL, woiH, woiL, WON / 4);

    // 3. QKV projection with fused RoPE + head-split + bf16 emit
    {
        dim3 grid(QKV_N / GBN, M_TOK / GBM);
        cgemm_tc_kernel<true><<<grid, 256, G_SMEM>>>(
            xrH, xrL, xiH, xiL, wqrH, wqrL, wqiH, wqiL,
            nullptr, nullptr, QKV_N, D_MODEL);
    }

    // 4. tensor-core flash attention (emits output splits directly)
    {
        dim3 grid(SEQ / 128, BHN);
        attn_tc_kernel<<<grid, 256, A_SMEM>>>();
    }

    // 5. output projection -> d_out
    {
        dim3 grid(D_MODEL / GBN, M_TOK / GBM);
        cgemm_tc_kernel<false><<<grid, 256, G_SMEM>>>(
            arH, arL, aiH, aiL, worH, worL, woiH, woiL,
            out, out + (size_t)M_TOK * D_MODEL, D_MODEL, D_MODEL);
    }
}

// round 11
// speedup vs baseline: 1.1681x; 1.0756x over previous
#include <cuda_runtime.h>
#include <cuda_bf16.h>
#include <math.h>
#include <stdint.h>

// Problem constants
#define D_MODEL 1024
#define N_HEADS 16
#define D_HEAD  64
#define BATCH   4
#define SEQ     512
#define M_TOK   (BATCH * SEQ)       // 2048
#define QKV_N   (3 * D_MODEL)       // 3072
#define BHN     (BATCH * N_HEADS)   // 64
#define QS      (BHN * SEQ * D_HEAD) // 2097152

// ---------------- device scratch (no runtime allocation allowed) ----------------
__device__ float g_rope_cos[SEQ * D_HEAD];
__device__ float g_rope_sin[SEQ * D_HEAD];

// bf16 hi/lo splits for projection GEMMs
#define XN   (M_TOK * D_MODEL)      // 2097152
#define WQN  (QKV_N * D_MODEL)      // 3145728
#define WON  (D_MODEL * D_MODEL)    // 1048576
__device__ __nv_bfloat16 g_xrH[XN],  g_xrL[XN],  g_xiH[XN],  g_xiL[XN];
__device__ __nv_bfloat16 g_wqrH[WQN], g_wqrL[WQN], g_wqiH[WQN], g_wqiL[WQN];
__device__ __nv_bfloat16 g_worH[WON], g_worL[WON], g_woiH[WON], g_woiL[WON];
__device__ __nv_bfloat16 g_arH[XN],  g_arL[XN],  g_aiH[XN],  g_aiL[XN];

// bf16 hi/lo splits for attention (written by fused QKV-GEMM epilogue)
// Q, K: [bh][s][d] token-major.  V: [bh][d][s] dim-major (transposed, B-frag ready).
__device__ __nv_bfloat16 g_QrH[QS], g_QrL[QS], g_QiH[QS], g_QiL[QS];
__device__ __nv_bfloat16 g_KrH[QS], g_KrL[QS], g_KiH[QS], g_KiL[QS];
__device__ __nv_bfloat16 g_VrH[QS], g_VrL[QS], g_ViH[QS], g_ViL[QS];

// ================= PTX helpers (baseline ISA only — no tcgen05) =================
__device__ __forceinline__ uint32_t smem_u32(const void* p) {
    uint32_t a;
    asm("{ .reg .u64 t; cvta.to.shared.u64 t, %1; cvt.u32.u64 %0, t; }" : "=r"(a) : "l"(p));
    return a;
}
__device__ __forceinline__ void cp_async16(uint32_t dst, const void* src) {
    asm volatile("cp.async.cg.shared.global [%0], [%1], 16;" :: "r"(dst), "l"(src));
}
__device__ __forceinline__ void cp_commit() {
    asm volatile("cp.async.commit_group;" ::: "memory");
}
template <int N> __device__ __forceinline__ void cp_wait() {
    asm volatile("cp.async.wait_group %0;" :: "n"(N) : "memory");
}
__device__ __forceinline__ void ldsm_x4(uint32_t* r, uint32_t a) {
    asm volatile("ldmatrix.sync.aligned.m8n8.x4.shared.b16 {%0,%1,%2,%3}, [%4];"
                 : "=r"(r[0]), "=r"(r[1]), "=r"(r[2]), "=r"(r[3]) : "r"(a));
}
// D += A(16x16 bf16, row) * B(16x8 bf16, col), fp32 accumulate
__device__ __forceinline__ void mma_bf16(float* c, const uint32_t* a, const uint32_t* b) {
    asm volatile(
        "mma.sync.aligned.m16n8k16.row.col.f32.bf16.bf16.f32 "
        "{%0,%1,%2,%3}, {%4,%5,%6,%7}, {%8,%9}, {%0,%1,%2,%3};"
        : "+f"(c[0]), "+f"(c[1]), "+f"(c[2]), "+f"(c[3])
        : "r"(a[0]), "r"(a[1]), "r"(a[2]), "r"(a[3]), "r"(b[0]), "r"(b[1]));
}
__device__ __forceinline__ void bsplit(float v, __nv_bfloat16& h, __nv_bfloat16& l) {
    h = __float2bfloat16_rn(v);
    l = __float2bfloat16_rn(v - __bfloat162float(h));
}
__device__ __forceinline__ uint32_t packbf2(__nv_bfloat16 a, __nv_bfloat16 b) {
    __nv_bfloat162 t{a, b};
    return *reinterpret_cast<uint32_t*>(&t);
}
#define SGNX2 0x80008000u

// ---------------- kernel 1: RoPE rotor table ----------------
__global__ void rope_table_kernel() {
    int i = blockIdx.x * blockDim.x + threadIdx.x;
    if (i >= SEQ * D_HEAD) return;
    int s = i / D_HEAD;
    int d = i % D_HEAD;
    float inv_freq = powf(10000.0f, -(float)d / (float)D_HEAD);
    float ang = (float)s * inv_freq;
    float sn, cs;
    sincosf(ang, &sn, &cs);
    g_rope_cos[i] = cs;
    g_rope_sin[i] = sn;
}

// ---------------- kernel 1b: complex hi/lo split (re, im) ----------------
__global__ void split_cx_kernel(const float* __restrict__ re, const float* __restrict__ im,
                                __nv_bfloat16* __restrict__ rH, __nv_bfloat16* __restrict__ rL,
                                __nv_bfloat16* __restrict__ iH, __nv_bfloat16* __restrict__ iL,
                                int n4) {
    int i = blockIdx.x * blockDim.x + threadIdx.x;
    if (i >= n4) return;
    float4 vr = ((const float4*)re)[i];
    float4 vi = ((const float4*)im)[i];
    __nv_bfloat16 h0, h1, h2, h3, l0, l1, l2, l3;

    bsplit(vr.x, h0, l0); bsplit(vr.y, h1, l1); bsplit(vr.z, h2, l2); bsplit(vr.w, h3, l3);
    ((uint32_t*)rH)[i * 2 + 0] = packbf2(h0, h1);
    ((uint32_t*)rH)[i * 2 + 1] = packbf2(h2, h3);
    ((uint32_t*)rL)[i * 2 + 0] = packbf2(l0, l1);
    ((uint32_t*)rL)[i * 2 + 1] = packbf2(l2, l3);

    bsplit(vi.x, h0, l0); bsplit(vi.y, h1, l1); bsplit(vi.z, h2, l2); bsplit(vi.w, h3, l3);
    ((uint32_t*)iH)[i * 2 + 0] = packbf2(h0, h1);
    ((uint32_t*)iH)[i * 2 + 1] = packbf2(h2, h3);
    ((uint32_t*)iL)[i * 2 + 0] = packbf2(l0, l1);
    ((uint32_t*)iL)[i * 2 + 1] = packbf2(l2, l3);
}

// ---------------- kernel 2: mma.sync complex GEMM  C = A @ B^T ----------------
// Direct form (12 HMMA per micro-tile): Cre = ArBr - AiBi (neg-Bi frags), Cim = ArBi + AiBr.
// CTA tile 128x128, K-stage 32, 2-stage cp.async pipeline, 8 warps (4m x 2n),
// warp tile 32x64. B fragments loaded per-nt16 inside loop (register pressure).
// FUSE_ROPE epilogue: applies RoPE + head-split + bf16 hi/lo emit for Q/K/V.
#define GBM 128
#define GBN 128
#define GBK 32
#define GPITCHB 80
#define A_COMP_B (GBM * GPITCHB)              // 10240
#define B_COMP_B (GBN * GPITCHB)              // 10240
#define STAGE_B  (4 * A_COMP_B + 4 * B_COMP_B) // 81920
#define G_SMEM   (2 * STAGE_B)                 // 163840

template <bool FUSE_ROPE>
__global__ __launch_bounds__(256, 1) void cgemm_tc_kernel(
    const __nv_bfloat16* __restrict__ ArH, const __nv_bfloat16* __restrict__ ArL,
    const __nv_bfloat16* __restrict__ AiH, const __nv_bfloat16* __restrict__ AiL,
    const __nv_bfloat16* __restrict__ BrH, const __nv_bfloat16* __restrict__ BrL,
    const __nv_bfloat16* __restrict__ BiH, const __nv_bfloat16* __restrict__ BiL,
    float* __restrict__ Cre, float* __restrict__ Cim,
    int N, int K)
{
    extern __shared__ __align__(128) char smem[];
    const uint32_t sb = smem_u32(smem);
    const int tid = threadIdx.x;
    const int lane = tid & 31;
    const int wid = tid >> 5;
    const int wm = wid & 3;           // 0..3 -> 32-row strip
    const int wn = wid >> 2;          // 0..1 -> 64-col strip
    const int m0 = blockIdx.y * GBM;
    const int n0 = blockIdx.x * GBN;

    const __nv_bfloat16* Ap[4] = {ArH, ArL, AiH, AiL};
    const __nv_bfloat16* Bp[4] = {BrH, BrL, BiH, BiL};

    auto load_stage = [&](int st, int k0) {
        uint32_t base = sb + st * STAGE_B;
#pragma unroll
        for (int i = 0; i < 8; i++) {                 // A: 2048 16B chunks
            int idx = tid + i * 256;
            int comp = idx >> 9;
            int rem = idx & 511;
            int row = rem >> 2;
            int ch = rem & 3;
            cp_async16(base + comp * A_COMP_B + row * GPITCHB + ch * 16,
                       Ap[comp] + (size_t)(m0 + row) * K + k0 + ch * 8);
        }
        uint32_t bbase = base + 4 * A_COMP_B;
#pragma unroll
        for (int i = 0; i < 8; i++) {                 // B: 2048 16B chunks
            int idx = tid + i * 256;
            int comp = idx >> 9;
            int rem = idx & 511;
            int row = rem >> 2;
            int ch = rem & 3;
            cp_async16(bbase + comp * B_COMP_B + row * GPITCHB + ch * 16,
                       Bp[comp] + (size_t)(n0 + row) * K + k0 + ch * 8);
        }
        cp_commit();
    };

    float cre[2][8][4];
    float cim[2][8][4];
#pragma unroll
    for (int mt = 0; mt < 2; mt++)
#pragma unroll
        for (int nt = 0; nt < 8; nt++)
#pragma unroll
            for (int q = 0; q < 4; q++) { cre[mt][nt][q] = 0.f; cim[mt][nt][q] = 0.f; }

    const int NC = K / GBK;
    load_stage(0, 0);

    const uint32_t krow = ((lane >> 4) & 1) * 8 + (lane & 7);
    const uint32_t koff = ((lane >> 3) & 1) * 16;

    for (int c = 0; c < NC; c++) {
        if (c + 1 < NC) { load_stage((c + 1) & 1, (c + 1) * GBK); cp_wait<1>(); }
        else            { cp_wait<0>(); }
        __syncthreads();

        const uint32_t abase = sb + (c & 1) * STAGE_B;
        const uint32_t bbase = abase + 4 * A_COMP_B;

#pragma unroll
        for (int ks = 0; ks < 2; ks++) {
            uint32_t af[4][2][4];
#pragma unroll
            for (int comp = 0; comp < 4; comp++)
#pragma unroll
                for (int mt = 0; mt < 2; mt++) {
                    uint32_t addr = abase + comp * A_COMP_B
                        + (uint32_t)(wm * 32 + mt * 16 + (lane & 15)) * GPITCHB
                        + ks * 32 + (lane >> 4) * 16;
                    ldsm_x4(af[comp][mt], addr);
                }
#pragma unroll
            for (int nt16 = 0; nt16 < 4; nt16++) {
                uint32_t bfr[4][4];          // [comp][4 regs = 2 b-frags]
                uint32_t baddr = bbase
                    + (uint32_t)(wn * 64 + nt16 * 16 + krow) * GPITCHB
                    + ks * 32 + koff;
#pragma unroll
                for (int comp = 0; comp < 4; comp++)
                    ldsm_x4(bfr[comp], baddr + comp * B_COMP_B);
#pragma unroll
                for (int hf = 0; hf < 2; hf++) {
                    int nt = nt16 * 2 + hf;
                    const uint32_t* bRH = bfr[0] + hf * 2;
                    const uint32_t* bRL = bfr[1] + hf * 2;
                    const uint32_t* bIH = bfr[2] + hf * 2;
                    const uint32_t* bIL = bfr[3] + hf * 2;
                    uint32_t nIH[2] = {bIH[0] ^ SGNX2, bIH[1] ^ SGNX2};
                    uint32_t nIL[2] = {bIL[0] ^ SGNX2, bIL[1] ^ SGNX2};
#pragma unroll
                    for (int mt = 0; mt < 2; mt++) {
                        float* cr = cre[mt][nt];
                        float* ci = cim[mt][nt];
                        mma_bf16(cr, af[0][mt], bRH);
                        mma_bf16(cr, af[0][mt], bRL);
                        mma_bf16(cr, af[1][mt], bRH);
                        mma_bf16(cr, af[2][mt], nIH);
                        mma_bf16(cr, af[2][mt], nIL);
                        mma_bf16(cr, af[3][mt], nIH);
                        mma_bf16(ci, af[0][mt], bIH);
                        mma_bf16(ci, af[0][mt], bIL);
                        mma_bf16(ci, af[1][mt], bIH);
                        mma_bf16(ci, af[2][mt], bRH);
                        mma_bf16(ci, af[2][mt], bRL);
                        mma_bf16(ci, af[3][mt], bRH);
                    }
                }
            }
        }
        __syncthreads();
    }

    // ---- epilogue ----
#pragma unroll
    for (int mt = 0; mt < 2; mt++) {
        int row0 = m0 + wm * 32 + mt * 16 + (lane >> 2);
#pragma unroll
        for (int nt = 0; nt < 8; nt++) {
            int col = n0 + wn * 64 + nt * 8 + (lane & 3) * 2;
            if (!FUSE_ROPE) {
                *(float2*)(Cre + (size_t)row0 * N + col) = {cre[mt][nt][0], cre[mt][nt][1]};
                *(float2*)(Cre + (size_t)(row0 + 8) * N + col) = {cre[mt][nt][2], cre[mt][nt][3]};
                *(float2*)(Cim + (size_t)row0 * N + col) = {cim[mt][nt][0], cim[mt][nt][1]};
                *(float2*)(Cim + (size_t)(row0 + 8) * N + col) = {cim[mt][nt][2], cim[mt][nt][3]};
            } else {
                int sec = col >> 10;          // 0=Q, 1=K, 2=V
                int hd = col & 1023;
                int h = hd >> 6;
                int d = hd & 63;
#pragma unroll
                for (int half = 0; half < 2; half++) {
                    int tkn = row0 + half * 8;
                    int b = tkn >> 9;
                    int s = tkn & 511;
                    int bh = (b << 4) + h;
                    float re0 = cre[mt][nt][half * 2 + 0];
                    float re1 = cre[mt][nt][half * 2 + 1];
                    float im0 = cim[mt][nt][half * 2 + 0];
                    float im1 = cim[mt][nt][half * 2 + 1];
                    if (sec == 2) {
                        size_t j = (size_t)bh * 32768 + (size_t)d * 512 + s;
                        __nv_bfloat16 H, L;
                        bsplit(re0, H, L); g_VrH[j] = H; g_VrL[j] = L;
                        bsplit(im0, H, L); g_ViH[j] = H; g_ViL[j] = L;
                        bsplit(re1, H, L); g_VrH[j + 512] = H; g_VrL[j + 512] = L;
                        bsplit(im1, H, L); g_ViH[j + 512] = H; g_ViL[j + 512] = L;
                    } else {
                        float2 rc = *(const float2*)(g_rope_cos + s * 64 + d);
                        float2 rs = *(const float2*)(g_rope_sin + s * 64 + d);
                        float ar0 = re0 * rc.x - im0 * rs.x;
                        float ai0 = re0 * rs.x + im0 * rc.x;
                        float ar1 = re1 * rc.y - im1 * rs.y;
                        float ai1 = re1 * rs.y + im1 * rc.y;
                        size_t i = (size_t)bh * 32768 + s * 64 + d;
                        __nv_bfloat16 h0, l0, h1, l1;
                        if (sec == 0) {
                            bsplit(ar0, h0, l0); bsplit(ar1, h1, l1);
                            *(uint32_t*)(g_QrH + i) = packbf2(h0, h1);
                            *(uint32_t*)(g_QrL + i) = packbf2(l0, l1);
                            bsplit(ai0, h0, l0); bsplit(ai1, h1, l1);
                            *(uint32_t*)(g_QiH + i) = packbf2(h0, h1);
                            *(uint32_t*)(g_QiL + i) = packbf2(l0, l1);
                        } else {
                            bsplit(ar0, h0, l0); bsplit(ar1, h1, l1);
                            *(uint32_t*)(g_KrH + i) = packbf2(h0, h1);
                            *(uint32_t*)(g_KrL + i) = packbf2(l0, l1);
                            bsplit(ai0, h0, l0); bsplit(ai1, h1, l1);
                            *(uint32_t*)(g_KiH + i) = packbf2(h0, h1);
                            *(uint32_t*)(g_KiL + i) = packbf2(l0, l1);
                        }
                    }
                }
            }
        }
    }
}

// ---------------- kernel 4: tensor-core flash attention (complex) ----------------
// CTA: 128 queries x one (b,h). 8 warps, warp w owns rows w*16..w*16+15.
// Epilogue emits bf16 hi/lo splits directly for the output projection.
#define AP    144
#define QCOMP (128 * AP)
#define KCOMP (64 * AP)
#define SQ_BYTES (4 * QCOMP)
#define ASTAGE   (8 * KCOMP)
#define A_SMEM   (SQ_BYTES + 2 * ASTAGE)  // 221184

__global__ __launch_bounds__(256, 1) void attn_tc_kernel() {
    extern __shared__ __align__(128) char smem[];
    const uint32_t sb = smem_u32(smem);
    const int tid = threadIdx.x;
    const int lane = tid & 31;
    const int w = tid >> 5;
    const int grp = lane >> 2;
    const int tq = lane & 3;
    const int q0 = blockIdx.x * 128;
    const int bh = blockIdx.y;
    const float scale = 0.125f;

    const __nv_bfloat16* gQ[4] = {g_QrH, g_QrL, g_QiH, g_QiL};
    const __nv_bfloat16* gK[4] = {g_KrH, g_KrL, g_KiH, g_KiL};
    const __nv_bfloat16* gV[4] = {g_VrH, g_VrL, g_ViH, g_ViL};
    const size_t hbQ = (size_t)bh * (SEQ * 64);

    {
#pragma unroll
        for (int it = 0; it < 16; it++) {
            int idx = tid + it * 256;
            int comp = idx >> 10;
            int rem = idx & 1023;
            int row = rem >> 3;
            int ch = rem & 7;
            cp_async16(sb + comp * QCOMP + row * AP + ch * 16,
                       gQ[comp] + hbQ + (size_t)(q0 + row) * 64 + ch * 8);
        }
    }
    auto load_stage = [&](int st, int c0) {
        uint32_t base = sb + SQ_BYTES + st * ASTAGE;
#pragma unroll
        for (int it = 0; it < 16; it++) {
            int idx = tid + it * 256;
            int comp = idx >> 9;
            int rem = idx & 511;
            int row = rem >> 3;
            int ch = rem & 7;
            const __nv_bfloat16* src;
            if (comp < 4) src = gK[comp] + hbQ + (size_t)(c0 + row) * 64 + ch * 8;
            else          src = gV[comp - 4] + hbQ + (size_t)row * SEQ + c0 + ch * 8;
            cp_async16(base + comp * KCOMP + row * AP + ch * 16, src);
        }
        cp_commit();
    };
    load_stage(0, 0);

    float or_[8][4], oi_[8][4];
#pragma unroll
    for (int nt = 0; nt < 8; nt++)
#pragma unroll
        for (int q = 0; q < 4; q++) { or_[nt][q] = 0.f; oi_[nt][q] = 0.f; }
    float m0 = -1e30f, m1 = -1e30f, l0 = 0.f, l1 = 0.f;

    for (int kc = 0; kc < 8; kc++) {
        if (kc < 7) { load_stage((kc + 1) & 1, (kc + 1) * 64); cp_wait<1>(); }
        else        { cp_wait<0>(); }
        __syncthreads();
        const uint32_t stg = sb + SQ_BYTES + (kc & 1) * ASTAGE;

        float sre[8][4], sim[8][4];
#pragma unroll
        for (int nt = 0; nt < 8; nt++)
#pragma unroll
            for (int q = 0; q < 4; q++) { sre[nt][q] = 0.f; sim[nt][q] = 0.f; }

        const uint32_t krow = ((lane >> 4) & 1) * 8 + (lane & 7);
        const uint32_t koff = ((lane >> 3) & 1) * 16;

#pragma unroll
        for (int ks = 0; ks < 4; ks++) {
            uint32_t qa = sb + (uint32_t)(w * 16 + (lane & 15)) * AP + ks * 32 + (lane >> 4) * 16;
            uint32_t qrH[4], qrL[4], qiH[4], qiL[4];
            ldsm_x4(qrH, qa + 0 * QCOMP);
            ldsm_x4(qrL, qa + 1 * QCOMP);
            ldsm_x4(qiH, qa + 2 * QCOMP);
            ldsm_x4(qiL, qa + 3 * QCOMP);
#pragma unroll
            for (int nt16 = 0; nt16 < 4; nt16++) {
                uint32_t kb = stg + (uint32_t)(nt16 * 16 + krow) * AP + ks * 32 + koff;
                uint32_t krH[4], krL[4], kiH[4], kiL[4];
                ldsm_x4(krH, kb + 0 * KCOMP);
                ldsm_x4(krL, kb + 1 * KCOMP);
                ldsm_x4(kiH, kb + 2 * KCOMP);
                ldsm_x4(kiL, kb + 3 * KCOMP);
#pragma unroll
                for (int hf = 0; hf < 2; hf++) {
                    int nt = nt16 * 2 + hf;
                    const uint32_t* bRH = krH + hf * 2;
                    const uint32_t* bRL = krL + hf * 2;
                    const uint32_t* bIH = kiH + hf * 2;
                    const uint32_t* bIL = kiL + hf * 2;
                    uint32_t nIH[2] = {bIH[0] ^ SGNX2, bIH[1] ^ SGNX2};
                    uint32_t nIL[2] = {bIL[0] ^ SGNX2, bIL[1] ^ SGNX2};
                    mma_bf16(sre[nt], qrH, bRH);
                    mma_bf16(sre[nt], qrH, bRL);
                    mma_bf16(sre[nt], qrL, bRH);
                    mma_bf16(sre[nt], qiH, bIH);
                    mma_bf16(sre[nt], qiH, bIL);
                    mma_bf16(sre[nt], qiL, bIH);
                    mma_bf16(sim[nt], qiH, bRH);
                    mma_bf16(sim[nt], qiH, bRL);
                    mma_bf16(sim[nt], qiL, bRH);
                    mma_bf16(sim[nt], qrH, nIH);
                    mma_bf16(sim[nt], qrH, nIL);
                    mma_bf16(sim[nt], qrL, nIH);
                }
            }
        }

        float cx0 = -1e30f, cx1 = -1e30f;
#pragma unroll
        for (int nt = 0; nt < 8; nt++) {
#pragma unroll
            for (int q = 0; q < 4; q++) { sre[nt][q] *= scale; sim[nt][q] *= scale; }
            cx0 = fmaxf(cx0, fmaxf(sre[nt][0], sre[nt][1]));
            cx1 = fmaxf(cx1, fmaxf(sre[nt][2], sre[nt][3]));
        }
        cx0 = fmaxf(cx0, __shfl_xor_sync(0xffffffffu, cx0, 1));
        cx0 = fmaxf(cx0, __shfl_xor_sync(0xffffffffu, cx0, 2));
        cx1 = fmaxf(cx1, __shfl_xor_sync(0xffffffffu, cx1, 1));
        cx1 = fmaxf(cx1, __shfl_xor_sync(0xffffffffu, cx1, 2));

        float nm0 = fmaxf(m0, cx0), nm1 = fmaxf(m1, cx1);
        float al0 = __expf(m0 - nm0), al1 = __expf(m1 - nm1);
        m0 = nm0; m1 = nm1;

        float rs0 = 0.f, rs1 = 0.f;
#pragma unroll
        for (int nt = 0; nt < 8; nt++) {
            float p0 = __expf(sre[nt][0] - nm0);
            float p1 = __expf(sre[nt][1] - nm0);
            float p2 = __expf(sre[nt][2] - nm1);
            float p3 = __expf(sre[nt][3] - nm1);
            rs0 += p0 + p1; rs1 += p2 + p3;
            float sn, cs;
            __sincosf(sim[nt][0], &sn, &cs); sre[nt][0] = p0 * cs; sim[nt][0] = p0 * sn;
            __sincosf(sim[nt][1], &sn, &cs); sre[nt][1] = p1 * cs; sim[nt][1] = p1 * sn;
            __sincosf(sim[nt][2], &sn, &cs); sre[nt][2] = p2 * cs; sim[nt][2] = p2 * sn;
            __sincosf(sim[nt][3], &sn, &cs); sre[nt][3] = p3 * cs; sim[nt][3] = p3 * sn;
        }
        rs0 += __shfl_xor_sync(0xffffffffu, rs0, 1);
        rs0 += __shfl_xor_sync(0xffffffffu, rs0, 2);
        rs1 += __shfl_xor_sync(0xffffffffu, rs1, 1);
        rs1 += __shfl_xor_sync(0xffffffffu, rs1, 2);
        l0 = l0 * al0 + rs0;
        l1 = l1 * al1 + rs1;
#pragma unroll
        for (int nt = 0; nt < 8; nt++) {
            or_[nt][0] *= al0; or_[nt][1] *= al0; or_[nt][2] *= al1; or_[nt][3] *= al1;
            oi_[nt][0] *= al0; oi_[nt][1] *= al0; oi_[nt][2] *= al1; oi_[nt][3] *= al1;
        }

        uint32_t wcH[4][4], wcL[4][4], wsH[4][4], wsL[4][4];
#pragma unroll
        for (int t = 0; t < 4; t++)
#pragma unroll
            for (int r = 0; r < 4; r++) {
                int nt = 2 * t + (r >> 1);
                int e = (r & 1) * 2;
                __nv_bfloat16 h0, lo0, h1, lo1;
                bsplit(sre[nt][e], h0, lo0); bsplit(sre[nt][e + 1], h1, lo1);
                wcH[t][r] = packbf2(h0, h1); wcL[t][r] = packbf2(lo0, lo1);
                bsplit(sim[nt][e], h0, lo0); bsplit(sim[nt][e + 1], h1, lo1);
                wsH[t][r] = packbf2(h0, h1); wsL[t][r] = packbf2(lo0, lo1);
            }

#pragma unroll
        for (int ks = 0; ks < 4; ks++) {
#pragma unroll
            for (int nt16 = 0; nt16 < 4; nt16++) {
                uint32_t vb = stg + (uint32_t)(nt16 * 16 + krow) * AP + ks * 32 + koff;
                uint32_t vrH[4], vrL[4], viH[4], viL[4];
                ldsm_x4(vrH, vb + 4 * KCOMP);
                ldsm_x4(vrL, vb + 5 * KCOMP);
                ldsm_x4(viH, vb + 6 * KCOMP);
                ldsm_x4(viL, vb + 7 * KCOMP);
#pragma unroll
                for (int hf = 0; hf < 2; hf++) {
                    int nt = nt16 * 2 + hf;
                    const uint32_t* bRH = vrH + hf * 2;
                    const uint32_t* bRL = vrL + hf * 2;
                    const uint32_t* bIH = viH + hf * 2;
                    const uint32_t* bIL = viL + hf * 2;
                    uint32_t nIH[2] = {bIH[0] ^ SGNX2, bIH[1] ^ SGNX2};
                    uint32_t nIL[2] = {bIL[0] ^ SGNX2, bIL[1] ^ SGNX2};
                    mma_bf16(or_[nt], wcH[ks], bRH);
                    mma_bf16(or_[nt], wcH[ks], bRL);
                    mma_bf16(or_[nt], wcL[ks], bRH);
                    mma_bf16(or_[nt], wsH[ks], nIH);
                    mma_bf16(or_[nt], wsH[ks], nIL);
                    mma_bf16(or_[nt], wsL[ks], nIH);
                    mma_bf16(oi_[nt], wcH[ks], bIH);
                    mma_bf16(oi_[nt], wcH[ks], bIL);
                    mma_bf16(oi_[nt], wcL[ks], bIH);
                    mma_bf16(oi_[nt], wsH[ks], bRH);
                    mma_bf16(oi_[nt], wsH[ks], bRL);
                    mma_bf16(oi_[nt], wsL[ks], bRH);
                }
            }
        }
        __syncthreads();
    }

    // ---- epilogue: emit bf16 hi/lo splits for output projection ----
    int b = bh >> 4;
    int h = bh & 15;
    float inv0 = 1.0f / l0, inv1 = 1.0f / l1;
    int qr0 = q0 + w * 16 + grp;
#pragma unroll
    for (int nt = 0; nt < 8; nt++) {
        int col = h * 64 + nt * 8 + tq * 2;
        size_t r0 = (size_t)(b * SEQ + qr0) * D_MODEL + col;
        size_t r1 = (size_t)(b * SEQ + qr0 + 8) * D_MODEL + col;
#pragma unroll
        for (int half = 0; half < 2; half++) {
            size_t rr = half ? r1 : r0;
            float inv = half ? inv1 : inv0;
            float ar0 = or_[nt][half * 2 + 0] * inv;
            float ar1 = or_[nt][half * 2 + 1] * inv;
            float ai0 = oi_[nt][half * 2 + 0] * inv;
            float ai1 = oi_[nt][half * 2 + 1] * inv;
            __nv_bfloat16 h0, lo0, h1, lo1;
            bsplit(ar0, h0, lo0); bsplit(ar1, h1, lo1);
            *(uint32_t*)(g_arH + rr) = packbf2(h0, h1);
            *(uint32_t*)(g_arL + rr) = packbf2(lo0, lo1);
            bsplit(ai0, h0, lo0); bsplit(ai1, h1, lo1);
            *(uint32_t*)(g_aiH + rr) = packbf2(h0, h1);
            *(uint32_t*)(g_aiL + rr) = packbf2(lo0, lo1);
        }
    }
}

// ---------------- launch ----------------
extern "C" void kernel_launch(void* const* d_in, const int* in_sizes, int n_in,
                              void* d_out, int out_size) {
    (void)in_sizes; (void)n_in; (void)out_size;
    const float* x_re    = (const float*)d_in[0];
    const float* x_im    = (const float*)d_in[1];
    const float* wqkv_re = (const float*)d_in[2];
    const float* wqkv_im = (const float*)d_in[3];
    const float* wo_re   = (const float*)d_in[4];
    const float* wo_im   = (const float*)d_in[5];
    float* out = (float*)d_out;

    __nv_bfloat16 *xrH, *xrL, *xiH, *xiL;
    __nv_bfloat16 *wqrH, *wqrL, *wqiH, *wqiL;
    __nv_bfloat16 *worH, *worL, *woiH, *woiL;
    __nv_bfloat16 *arH, *arL, *aiH, *aiL;
    cudaGetSymbolAddress((void**)&xrH, g_xrH);   cudaGetSymbolAddress((void**)&xrL, g_xrL);
    cudaGetSymbolAddress((void**)&xiH, g_xiH);   cudaGetSymbolAddress((void**)&xiL, g_xiL);
    cudaGetSymbolAddress((void**)&wqrH, g_wqrH); cudaGetSymbolAddress((void**)&wqrL, g_wqrL);
    cudaGetSymbolAddress((void**)&wqiH, g_wqiH); cudaGetSymbolAddress((void**)&wqiL, g_wqiL);
    cudaGetSymbolAddress((void**)&worH, g_worH); cudaGetSymbolAddress((void**)&worL, g_worL);
    cudaGetSymbolAddress((void**)&woiH, g_woiH); cudaGetSymbolAddress((void**)&woiL, g_woiL);
    cudaGetSymbolAddress((void**)&arH, g_arH);   cudaGetSymbolAddress((void**)&arL, g_arL);
    cudaGetSymbolAddress((void**)&aiH, g_aiH);   cudaGetSymbolAddress((void**)&aiL, g_aiL);

    cudaFuncSetAttribute(cgemm_tc_kernel<true>,
                         cudaFuncAttributeMaxDynamicSharedMemorySize, G_SMEM);
    cudaFuncSetAttribute(cgemm_tc_kernel<false>,
                         cudaFuncAttributeMaxDynamicSharedMemorySize, G_SMEM);
    cudaFuncSetAttribute(attn_tc_kernel,
                         cudaFuncAttributeMaxDynamicSharedMemorySize, A_SMEM);

    // 1. rope table
    rope_table_kernel<<<(SEQ * D_HEAD + 255) / 256, 256>>>();

    // 2. complex hi/lo splits of inputs + weights
    split_cx_kernel<<<(XN / 4 + 255) / 256, 256>>>(x_re, x_im, xrH, xrL, xiH, xiL, XN / 4);
    split_cx_kernel<<<(WQN / 4 + 255) / 256, 256>>>(wqkv_re, wqkv_im, wqrH, wqrL, wqiH, wqiL, WQN / 4);
    split_cx_kernel<<<(WON / 4 + 255) / 256, 256>>>(wo_re, wo_im, worH, worL, woiH, woiL, WON / 4);

    // 3. QKV projection with fused RoPE + head-split + bf16 emit
    {
        dim3 grid(QKV_N / GBN, M_TOK / GBM);
        cgemm_tc_kernel<true><<<grid, 256, G_SMEM>>>(
            xrH, xrL, xiH, xiL, wqrH, wqrL, wqiH, wqiL,
            nullptr, nullptr, QKV_N, D_MODEL);
    }

    // 4. tensor-core flash attention (emits output splits directly)
    {
        dim3 grid(SEQ / 128, BHN);
        attn_tc_kernel<<<grid, 256, A_SMEM>>>();
    }

    // 5. output projection -> d_out
    {
        dim3 grid(D_MODEL / GBN, M_TOK / GBM);
        cgemm_tc_kernel<false><<<grid, 256, G_SMEM>>>(
            arH, arL, aiH, aiL, worH, worL, woiH, woiL,
            out, out + (size_t)M_TOK * D_MODEL, D_MODEL, D_MODEL);
    }
}

// round 12
// speedup vs baseline: 1.2453x; 1.0661x over previous
#include <cuda_runtime.h>
#include <cuda_bf16.h>
#include <cuda_fp16.h>
#include <math.h>
#include <stdint.h>

// Problem constants
#define D_MODEL 1024
#define N_HEADS 16
#define D_HEAD  64
#define BATCH   4
#define SEQ     512
#define M_TOK   (BATCH * SEQ)       // 2048
#define QKV_N   (3 * D_MODEL)       // 3072
#define BHN     (BATCH * N_HEADS)   // 64
#define QS      (BHN * SEQ * D_HEAD) // 2097152

// ---------------- device scratch (no runtime allocation allowed) ----------------
__device__ float g_rope_cos[SEQ * D_HEAD];
__device__ float g_rope_sin[SEQ * D_HEAD];

// bf16 hi/lo splits for projection GEMMs
#define XN   (M_TOK * D_MODEL)      // 2097152
#define WQN  (QKV_N * D_MODEL)      // 3145728
#define WON  (D_MODEL * D_MODEL)    // 1048576
__device__ __nv_bfloat16 g_xrH[XN],  g_xrL[XN],  g_xiH[XN],  g_xiL[XN];
__device__ __nv_bfloat16 g_wqrH[WQN], g_wqrL[WQN], g_wqiH[WQN], g_wqiL[WQN];
__device__ __nv_bfloat16 g_worH[WON], g_worL[WON], g_woiH[WON], g_woiL[WON];
__device__ __nv_bfloat16 g_arH[XN],  g_arL[XN],  g_aiH[XN],  g_aiL[XN];

// attention operands (written by fused QKV-GEMM epilogue)
// Q, K: bf16 hi/lo, [bh][s][d] token-major, Q pre-scaled by 1/8.
// V: single fp16, [bh][d][s] dim-major (transposed, B-frag ready).
__device__ __nv_bfloat16 g_QrH[QS], g_QrL[QS], g_QiH[QS], g_QiL[QS];
__device__ __nv_bfloat16 g_KrH[QS], g_KrL[QS], g_KiH[QS], g_KiL[QS];
__device__ __half g_VrF[QS], g_ViF[QS];

// ================= PTX helpers (baseline ISA only — no tcgen05) =================
__device__ __forceinline__ uint32_t smem_u32(const void* p) {
    uint32_t a;
    asm("{ .reg .u64 t; cvta.to.shared.u64 t, %1; cvt.u32.u64 %0, t; }" : "=r"(a) : "l"(p));
    return a;
}
__device__ __forceinline__ void cp_async16(uint32_t dst, const void* src) {
    asm volatile("cp.async.cg.shared.global [%0], [%1], 16;" :: "r"(dst), "l"(src));
}
__device__ __forceinline__ void cp_commit() {
    asm volatile("cp.async.commit_group;" ::: "memory");
}
template <int N> __device__ __forceinline__ void cp_wait() {
    asm volatile("cp.async.wait_group %0;" :: "n"(N) : "memory");
}
__device__ __forceinline__ void ldsm_x4(uint32_t* r, uint32_t a) {
    asm volatile("ldmatrix.sync.aligned.m8n8.x4.shared.b16 {%0,%1,%2,%3}, [%4];"
                 : "=r"(r[0]), "=r"(r[1]), "=r"(r[2]), "=r"(r[3]) : "r"(a));
}
// D += A(16x16 bf16, row) * B(16x8 bf16, col), fp32 accumulate
__device__ __forceinline__ void mma_bf16(float* c, const uint32_t* a, const uint32_t* b) {
    asm volatile(
        "mma.sync.aligned.m16n8k16.row.col.f32.bf16.bf16.f32 "
        "{%0,%1,%2,%3}, {%4,%5,%6,%7}, {%8,%9}, {%0,%1,%2,%3};"
        : "+f"(c[0]), "+f"(c[1]), "+f"(c[2]), "+f"(c[3])
        : "r"(a[0]), "r"(a[1]), "r"(a[2]), "r"(a[3]), "r"(b[0]), "r"(b[1]));
}
// D += A(16x16 f16, row) * B(16x8 f16, col), fp32 accumulate
__device__ __forceinline__ void mma_f16(float* c, const uint32_t* a, const uint32_t* b) {
    asm volatile(
        "mma.sync.aligned.m16n8k16.row.col.f32.f16.f16.f32 "
        "{%0,%1,%2,%3}, {%4,%5,%6,%7}, {%8,%9}, {%0,%1,%2,%3};"
        : "+f"(c[0]), "+f"(c[1]), "+f"(c[2]), "+f"(c[3])
        : "r"(a[0]), "r"(a[1]), "r"(a[2]), "r"(a[3]), "r"(b[0]), "r"(b[1]));
}
__device__ __forceinline__ void bsplit(float v, __nv_bfloat16& h, __nv_bfloat16& l) {
    h = __float2bfloat16_rn(v);
    l = __float2bfloat16_rn(v - __bfloat162float(h));
}
__device__ __forceinline__ uint32_t packbf2(__nv_bfloat16 a, __nv_bfloat16 b) {
    __nv_bfloat162 t{a, b};
    return *reinterpret_cast<uint32_t*>(&t);
}
__device__ __forceinline__ uint32_t packh2(float a, float b) {
    __half2 t{__float2half_rn(a), __float2half_rn(b)};
    return *reinterpret_cast<uint32_t*>(&t);
}
#define SGNX2 0x80008000u

// ---------------- kernel 1: RoPE rotor table ----------------
__global__ void rope_table_kernel() {
    int i = blockIdx.x * blockDim.x + threadIdx.x;
    if (i >= SEQ * D_HEAD) return;
    int s = i / D_HEAD;
    int d = i % D_HEAD;
    float inv_freq = powf(10000.0f, -(float)d / (float)D_HEAD);
    float ang = (float)s * inv_freq;
    float sn, cs;
    sincosf(ang, &sn, &cs);
    g_rope_cos[i] = cs;
    g_rope_sin[i] = sn;
}

// ---------------- kernel 1b: complex hi/lo split (re, im) ----------------
__global__ void split_cx_kernel(const float* __restrict__ re, const float* __restrict__ im,
                                __nv_bfloat16* __restrict__ rH, __nv_bfloat16* __restrict__ rL,
                                __nv_bfloat16* __restrict__ iH, __nv_bfloat16* __restrict__ iL,
                                int n4) {
    int i = blockIdx.x * blockDim.x + threadIdx.x;
    if (i >= n4) return;
    float4 vr = ((const float4*)re)[i];
    float4 vi = ((const float4*)im)[i];
    __nv_bfloat16 h0, h1, h2, h3, l0, l1, l2, l3;

    bsplit(vr.x, h0, l0); bsplit(vr.y, h1, l1); bsplit(vr.z, h2, l2); bsplit(vr.w, h3, l3);
    ((uint32_t*)rH)[i * 2 + 0] = packbf2(h0, h1);
    ((uint32_t*)rH)[i * 2 + 1] = packbf2(h2, h3);
    ((uint32_t*)rL)[i * 2 + 0] = packbf2(l0, l1);
    ((uint32_t*)rL)[i * 2 + 1] = packbf2(l2, l3);

    bsplit(vi.x, h0, l0); bsplit(vi.y, h1, l1); bsplit(vi.z, h2, l2); bsplit(vi.w, h3, l3);
    ((uint32_t*)iH)[i * 2 + 0] = packbf2(h0, h1);
    ((uint32_t*)iH)[i * 2 + 1] = packbf2(h2, h3);
    ((uint32_t*)iL)[i * 2 + 0] = packbf2(l0, l1);
    ((uint32_t*)iL)[i * 2 + 1] = packbf2(l2, l3);
}

// ---------------- kernel 2: mma.sync complex GEMM  C = A @ B^T ----------------
// Direct form (12 HMMA per micro-tile): Cre = ArBr - AiBi (neg-Bi frags), Cim = ArBi + AiBr.
// CTA tile 128x128, K-stage 32, 2-stage cp.async pipeline, 8 warps (4m x 2n),
// warp tile 32x64. FUSE_ROPE epilogue: RoPE + head-split + Q/K bf16 splits (Q
// pre-scaled by 1/8) + V fp16 emit.
#define GBM 128
#define GBN 128
#define GBK 32
#define GPITCHB 80
#define A_COMP_B (GBM * GPITCHB)              // 10240
#define B_COMP_B (GBN * GPITCHB)              // 10240
#define STAGE_B  (4 * A_COMP_B + 4 * B_COMP_B) // 81920
#define G_SMEM   (2 * STAGE_B)                 // 163840

template <bool FUSE_ROPE>
__global__ __launch_bounds__(256, 1) void cgemm_tc_kernel(
    const __nv_bfloat16* __restrict__ ArH, const __nv_bfloat16* __restrict__ ArL,
    const __nv_bfloat16* __restrict__ AiH, const __nv_bfloat16* __restrict__ AiL,
    const __nv_bfloat16* __restrict__ BrH, const __nv_bfloat16* __restrict__ BrL,
    const __nv_bfloat16* __restrict__ BiH, const __nv_bfloat16* __restrict__ BiL,
    float* __restrict__ Cre, float* __restrict__ Cim,
    int N, int K)
{
    extern __shared__ __align__(128) char smem[];
    const uint32_t sb = smem_u32(smem);
    const int tid = threadIdx.x;
    const int lane = tid & 31;
    const int wid = tid >> 5;
    const int wm = wid & 3;
    const int wn = wid >> 2;
    const int m0 = blockIdx.y * GBM;
    const int n0 = blockIdx.x * GBN;

    const __nv_bfloat16* Ap[4] = {ArH, ArL, AiH, AiL};
    const __nv_bfloat16* Bp[4] = {BrH, BrL, BiH, BiL};

    auto load_stage = [&](int st, int k0) {
        uint32_t base = sb + st * STAGE_B;
#pragma unroll
        for (int i = 0; i < 8; i++) {
            int idx = tid + i * 256;
            int comp = idx >> 9;
            int rem = idx & 511;
            int row = rem >> 2;
            int ch = rem & 3;
            cp_async16(base + comp * A_COMP_B + row * GPITCHB + ch * 16,
                       Ap[comp] + (size_t)(m0 + row) * K + k0 + ch * 8);
        }
        uint32_t bbase = base + 4 * A_COMP_B;
#pragma unroll
        for (int i = 0; i < 8; i++) {
            int idx = tid + i * 256;
            int comp = idx >> 9;
            int rem = idx & 511;
            int row = rem >> 2;
            int ch = rem & 3;
            cp_async16(bbase + comp * B_COMP_B + row * GPITCHB + ch * 16,
                       Bp[comp] + (size_t)(n0 + row) * K + k0 + ch * 8);
        }
        cp_commit();
    };

    float cre[2][8][4];
    float cim[2][8][4];
#pragma unroll
    for (int mt = 0; mt < 2; mt++)
#pragma unroll
        for (int nt = 0; nt < 8; nt++)
#pragma unroll
            for (int q = 0; q < 4; q++) { cre[mt][nt][q] = 0.f; cim[mt][nt][q] = 0.f; }

    const int NC = K / GBK;
    load_stage(0, 0);

    const uint32_t krow = ((lane >> 4) & 1) * 8 + (lane & 7);
    const uint32_t koff = ((lane >> 3) & 1) * 16;

    for (int c = 0; c < NC; c++) {
        if (c + 1 < NC) { load_stage((c + 1) & 1, (c + 1) * GBK); cp_wait<1>(); }
        else            { cp_wait<0>(); }
        __syncthreads();

        const uint32_t abase = sb + (c & 1) * STAGE_B;
        const uint32_t bbase = abase + 4 * A_COMP_B;

#pragma unroll
        for (int ks = 0; ks < 2; ks++) {
            uint32_t af[4][2][4];
#pragma unroll
            for (int comp = 0; comp < 4; comp++)
#pragma unroll
                for (int mt = 0; mt < 2; mt++) {
                    uint32_t addr = abase + comp * A_COMP_B
                        + (uint32_t)(wm * 32 + mt * 16 + (lane & 15)) * GPITCHB
                        + ks * 32 + (lane >> 4) * 16;
                    ldsm_x4(af[comp][mt], addr);
                }
#pragma unroll
            for (int nt16 = 0; nt16 < 4; nt16++) {
                uint32_t bfr[4][4];
                uint32_t baddr = bbase
                    + (uint32_t)(wn * 64 + nt16 * 16 + krow) * GPITCHB
                    + ks * 32 + koff;
#pragma unroll
                for (int comp = 0; comp < 4; comp++)
                    ldsm_x4(bfr[comp], baddr + comp * B_COMP_B);
#pragma unroll
                for (int hf = 0; hf < 2; hf++) {
                    int nt = nt16 * 2 + hf;
                    const uint32_t* bRH = bfr[0] + hf * 2;
                    const uint32_t* bRL = bfr[1] + hf * 2;
                    const uint32_t* bIH = bfr[2] + hf * 2;
                    const uint32_t* bIL = bfr[3] + hf * 2;
                    uint32_t nIH[2] = {bIH[0] ^ SGNX2, bIH[1] ^ SGNX2};
                    uint32_t nIL[2] = {bIL[0] ^ SGNX2, bIL[1] ^ SGNX2};
#pragma unroll
                    for (int mt = 0; mt < 2; mt++) {
                        float* cr = cre[mt][nt];
                        float* ci = cim[mt][nt];
                        mma_bf16(cr, af[0][mt], bRH);
                        mma_bf16(cr, af[0][mt], bRL);
                        mma_bf16(cr, af[1][mt], bRH);
                        mma_bf16(cr, af[2][mt], nIH);
                        mma_bf16(cr, af[2][mt], nIL);
                        mma_bf16(cr, af[3][mt], nIH);
                        mma_bf16(ci, af[0][mt], bIH);
                        mma_bf16(ci, af[0][mt], bIL);
                        mma_bf16(ci, af[1][mt], bIH);
                        mma_bf16(ci, af[2][mt], bRH);
                        mma_bf16(ci, af[2][mt], bRL);
                        mma_bf16(ci, af[3][mt], bRH);
                    }
                }
            }
        }
        __syncthreads();
    }

    // ---- epilogue ----
#pragma unroll
    for (int mt = 0; mt < 2; mt++) {
        int row0 = m0 + wm * 32 + mt * 16 + (lane >> 2);
#pragma unroll
        for (int nt = 0; nt < 8; nt++) {
            int col = n0 + wn * 64 + nt * 8 + (lane & 3) * 2;
            if (!FUSE_ROPE) {
                *(float2*)(Cre + (size_t)row0 * N + col) = {cre[mt][nt][0], cre[mt][nt][1]};
                *(float2*)(Cre + (size_t)(row0 + 8) * N + col) = {cre[mt][nt][2], cre[mt][nt][3]};
                *(float2*)(Cim + (size_t)row0 * N + col) = {cim[mt][nt][0], cim[mt][nt][1]};
                *(float2*)(Cim + (size_t)(row0 + 8) * N + col) = {cim[mt][nt][2], cim[mt][nt][3]};
            } else {
                int sec = col >> 10;          // 0=Q, 1=K, 2=V
                int hd = col & 1023;
                int h = hd >> 6;
                int d = hd & 63;
#pragma unroll
                for (int half = 0; half < 2; half++) {
                    int tkn = row0 + half * 8;
                    int b = tkn >> 9;
                    int s = tkn & 511;
                    int bh = (b << 4) + h;
                    float re0 = cre[mt][nt][half * 2 + 0];
                    float re1 = cre[mt][nt][half * 2 + 1];
                    float im0 = cim[mt][nt][half * 2 + 0];
                    float im1 = cim[mt][nt][half * 2 + 1];
                    if (sec == 2) {
                        size_t j = (size_t)bh * 32768 + (size_t)d * 512 + s;
                        g_VrF[j] = __float2half_rn(re0);
                        g_ViF[j] = __float2half_rn(im0);
                        g_VrF[j + 512] = __float2half_rn(re1);
                        g_ViF[j + 512] = __float2half_rn(im1);
                    } else {
                        float2 rc = *(const float2*)(g_rope_cos + s * 64 + d);
                        float2 rs = *(const float2*)(g_rope_sin + s * 64 + d);
                        float ar0 = re0 * rc.x - im0 * rs.x;
                        float ai0 = re0 * rs.x + im0 * rc.x;
                        float ar1 = re1 * rc.y - im1 * rs.y;
                        float ai1 = re1 * rs.y + im1 * rc.y;
                        size_t i = (size_t)bh * 32768 + s * 64 + d;
                        __nv_bfloat16 h0, l0, h1, l1;
                        if (sec == 0) {
                            // fold the 1/sqrt(Dh) score scale into Q
                            ar0 *= 0.125f; ai0 *= 0.125f; ar1 *= 0.125f; ai1 *= 0.125f;
                            bsplit(ar0, h0, l0); bsplit(ar1, h1, l1);
                            *(uint32_t*)(g_QrH + i) = packbf2(h0, h1);
                            *(uint32_t*)(g_QrL + i) = packbf2(l0, l1);
                            bsplit(ai0, h0, l0); bsplit(ai1, h1, l1);
                            *(uint32_t*)(g_QiH + i) = packbf2(h0, h1);
                            *(uint32_t*)(g_QiL + i) = packbf2(l0, l1);
                        } else {
                            bsplit(ar0, h0, l0); bsplit(ar1, h1, l1);
                            *(uint32_t*)(g_KrH + i) = packbf2(h0, h1);
                            *(uint32_t*)(g_KrL + i) = packbf2(l0, l1);
                            bsplit(ai0, h0, l0); bsplit(ai1, h1, l1);
                            *(uint32_t*)(g_KiH + i) = packbf2(h0, h1);
                            *(uint32_t*)(g_KiL + i) = packbf2(l0, l1);
                        }
                    }
                }
            }
        }
    }
}

// ---------------- kernel 4: tensor-core flash attention (complex) ----------------
// CTA: 128 queries x one (b,h). 8 warps, warp w owns rows w*16..w*16+15.
// Scores: 3-term bf16 split (Q pre-scaled). PV: single-term fp16 (4 MMAs).
// Epilogue emits bf16 hi/lo splits directly for the output projection.
#define AP    144
#define QCOMP (128 * AP)
#define KCOMP (64 * AP)
#define SQ_BYTES (4 * QCOMP)
#define ASTAGE   (6 * KCOMP)              // 4 K bf16 comps + 2 V fp16 comps
#define A_SMEM   (SQ_BYTES + 2 * ASTAGE)  // 184320

__global__ __launch_bounds__(256, 1) void attn_tc_kernel() {
    extern __shared__ __align__(128) char smem[];
    const uint32_t sb = smem_u32(smem);
    const int tid = threadIdx.x;
    const int lane = tid & 31;
    const int w = tid >> 5;
    const int grp = lane >> 2;
    const int tq = lane & 3;
    const int q0 = blockIdx.x * 128;
    const int bh = blockIdx.y;

    const __nv_bfloat16* gQ[4] = {g_QrH, g_QrL, g_QiH, g_QiL};
    const __nv_bfloat16* gK[4] = {g_KrH, g_KrL, g_KiH, g_KiL};
    const __half* gV[2] = {g_VrF, g_ViF};
    const size_t hbQ = (size_t)bh * (SEQ * 64);

    {
#pragma unroll
        for (int it = 0; it < 16; it++) {
            int idx = tid + it * 256;
            int comp = idx >> 10;
            int rem = idx & 1023;
            int row = rem >> 3;
            int ch = rem & 7;
            cp_async16(sb + comp * QCOMP + row * AP + ch * 16,
                       gQ[comp] + hbQ + (size_t)(q0 + row) * 64 + ch * 8);
        }
    }
    auto load_stage = [&](int st, int c0) {
        uint32_t base = sb + SQ_BYTES + st * ASTAGE;
#pragma unroll
        for (int it = 0; it < 12; it++) {
            int idx = tid + it * 256;
            int comp = idx >> 9;              // 0..5
            int rem = idx & 511;
            int row = rem >> 3;
            int ch = rem & 7;
            const void* src;
            if (comp < 4) src = gK[comp] + hbQ + (size_t)(c0 + row) * 64 + ch * 8;
            else          src = gV[comp - 4] + hbQ + (size_t)row * SEQ + c0 + ch * 8;
            cp_async16(base + comp * KCOMP + row * AP + ch * 16, src);
        }
        cp_commit();
    };
    load_stage(0, 0);

    float or_[8][4], oi_[8][4];
#pragma unroll
    for (int nt = 0; nt < 8; nt++)
#pragma unroll
        for (int q = 0; q < 4; q++) { or_[nt][q] = 0.f; oi_[nt][q] = 0.f; }
    float m0 = -1e30f, m1 = -1e30f, l0 = 0.f, l1 = 0.f;

    for (int kc = 0; kc < 8; kc++) {
        if (kc < 7) { load_stage((kc + 1) & 1, (kc + 1) * 64); cp_wait<1>(); }
        else        { cp_wait<0>(); }
        __syncthreads();
        const uint32_t stg = sb + SQ_BYTES + (kc & 1) * ASTAGE;

        float sre[8][4], sim[8][4];
#pragma unroll
        for (int nt = 0; nt < 8; nt++)
#pragma unroll
            for (int q = 0; q < 4; q++) { sre[nt][q] = 0.f; sim[nt][q] = 0.f; }

        const uint32_t krow = ((lane >> 4) & 1) * 8 + (lane & 7);
        const uint32_t koff = ((lane >> 3) & 1) * 16;

#pragma unroll
        for (int ks = 0; ks < 4; ks++) {
            uint32_t qa = sb + (uint32_t)(w * 16 + (lane & 15)) * AP + ks * 32 + (lane >> 4) * 16;
            uint32_t qrH[4], qrL[4], qiH[4], qiL[4];
            ldsm_x4(qrH, qa + 0 * QCOMP);
            ldsm_x4(qrL, qa + 1 * QCOMP);
            ldsm_x4(qiH, qa + 2 * QCOMP);
            ldsm_x4(qiL, qa + 3 * QCOMP);
#pragma unroll
            for (int nt16 = 0; nt16 < 4; nt16++) {
                uint32_t kb = stg + (uint32_t)(nt16 * 16 + krow) * AP + ks * 32 + koff;
                uint32_t krH[4], krL[4], kiH[4], kiL[4];
                ldsm_x4(krH, kb + 0 * KCOMP);
                ldsm_x4(krL, kb + 1 * KCOMP);
                ldsm_x4(kiH, kb + 2 * KCOMP);
                ldsm_x4(kiL, kb + 3 * KCOMP);
#pragma unroll
                for (int hf = 0; hf < 2; hf++) {
                    int nt = nt16 * 2 + hf;
                    const uint32_t* bRH = krH + hf * 2;
                    const uint32_t* bRL = krL + hf * 2;
                    const uint32_t* bIH = kiH + hf * 2;
                    const uint32_t* bIL = kiL + hf * 2;
                    uint32_t nIH[2] = {bIH[0] ^ SGNX2, bIH[1] ^ SGNX2};
                    uint32_t nIL[2] = {bIL[0] ^ SGNX2, bIL[1] ^ SGNX2};
                    mma_bf16(sre[nt], qrH, bRH);
                    mma_bf16(sre[nt], qrH, bRL);
                    mma_bf16(sre[nt], qrL, bRH);
                    mma_bf16(sre[nt], qiH, bIH);
                    mma_bf16(sre[nt], qiH, bIL);
                    mma_bf16(sre[nt], qiL, bIH);
                    mma_bf16(sim[nt], qiH, bRH);
                    mma_bf16(sim[nt], qiH, bRL);
                    mma_bf16(sim[nt], qiL, bRH);
                    mma_bf16(sim[nt], qrH, nIH);
                    mma_bf16(sim[nt], qrH, nIL);
                    mma_bf16(sim[nt], qrL, nIH);
                }
            }
        }

        // (scale already folded into Q at the QKV epilogue)
        float cx0 = -1e30f, cx1 = -1e30f;
#pragma unroll
        for (int nt = 0; nt < 8; nt++) {
            cx0 = fmaxf(cx0, fmaxf(sre[nt][0], sre[nt][1]));
            cx1 = fmaxf(cx1, fmaxf(sre[nt][2], sre[nt][3]));
        }
        cx0 = fmaxf(cx0, __shfl_xor_sync(0xffffffffu, cx0, 1));
        cx0 = fmaxf(cx0, __shfl_xor_sync(0xffffffffu, cx0, 2));
        cx1 = fmaxf(cx1, __shfl_xor_sync(0xffffffffu, cx1, 1));
        cx1 = fmaxf(cx1, __shfl_xor_sync(0xffffffffu, cx1, 2));

        float nm0 = fmaxf(m0, cx0), nm1 = fmaxf(m1, cx1);
        float al0 = __expf(m0 - nm0), al1 = __expf(m1 - nm1);
        m0 = nm0; m1 = nm1;

        float rs0 = 0.f, rs1 = 0.f;
#pragma unroll
        for (int nt = 0; nt < 8; nt++) {
            float p0 = __expf(sre[nt][0] - nm0);
            float p1 = __expf(sre[nt][1] - nm0);
            float p2 = __expf(sre[nt][2] - nm1);
            float p3 = __expf(sre[nt][3] - nm1);
            rs0 += p0 + p1; rs1 += p2 + p3;
            float sn, cs;
            __sincosf(sim[nt][0], &sn, &cs); sre[nt][0] = p0 * cs; sim[nt][0] = p0 * sn;
            __sincosf(sim[nt][1], &sn, &cs); sre[nt][1] = p1 * cs; sim[nt][1] = p1 * sn;
            __sincosf(sim[nt][2], &sn, &cs); sre[nt][2] = p2 * cs; sim[nt][2] = p2 * sn;
            __sincosf(sim[nt][3], &sn, &cs); sre[nt][3] = p3 * cs; sim[nt][3] = p3 * sn;
        }
        rs0 += __shfl_xor_sync(0xffffffffu, rs0, 1);
        rs0 += __shfl_xor_sync(0xffffffffu, rs0, 2);
        rs1 += __shfl_xor_sync(0xffffffffu, rs1, 1);
        rs1 += __shfl_xor_sync(0xffffffffu, rs1, 2);
        l0 = l0 * al0 + rs0;
        l1 = l1 * al1 + rs1;
#pragma unroll
        for (int nt = 0; nt < 8; nt++) {
            or_[nt][0] *= al0; or_[nt][1] *= al0; or_[nt][2] *= al1; or_[nt][3] *= al1;
            oi_[nt][0] *= al0; oi_[nt][1] *= al0; oi_[nt][2] *= al1; oi_[nt][3] *= al1;
        }

        // weight C-frags -> fp16 A-frags (single precision term)
        uint32_t wcF[4][4], wsF[4][4];
#pragma unroll
        for (int t = 0; t < 4; t++)
#pragma unroll
            for (int r = 0; r < 4; r++) {
                int nt = 2 * t + (r >> 1);
                int e = (r & 1) * 2;
                wcF[t][r] = packh2(sre[nt][e], sre[nt][e + 1]);
                wsF[t][r] = packh2(sim[nt][e], sim[nt][e + 1]);
            }

        // PV (fp16): out_r += Wc*Vr - Ws*Vi ; out_i += Wc*Vi + Ws*Vr
#pragma unroll
        for (int ks = 0; ks < 4; ks++) {
#pragma unroll
            for (int nt16 = 0; nt16 < 4; nt16++) {
                uint32_t vb = stg + (uint32_t)(nt16 * 16 + krow) * AP + ks * 32 + koff;
                uint32_t vrF[4], viF[4];
                ldsm_x4(vrF, vb + 4 * KCOMP);
                ldsm_x4(viF, vb + 5 * KCOMP);
#pragma unroll
                for (int hf = 0; hf < 2; hf++) {
                    int nt = nt16 * 2 + hf;
                    const uint32_t* bRF = vrF + hf * 2;
                    const uint32_t* bIF = viF + hf * 2;
                    uint32_t nIF[2] = {bIF[0] ^ SGNX2, bIF[1] ^ SGNX2};
                    mma_f16(or_[nt], wcF[ks], bRF);
                    mma_f16(or_[nt], wsF[ks], nIF);
                    mma_f16(oi_[nt], wcF[ks], bIF);
                    mma_f16(oi_[nt], wsF[ks], bRF);
                }
            }
        }
        __syncthreads();
    }

    // ---- epilogue: emit bf16 hi/lo splits for output projection ----
    int b = bh >> 4;
    int h = bh & 15;
    float inv0 = 1.0f / l0, inv1 = 1.0f / l1;
    int qr0 = q0 + w * 16 + grp;
#pragma unroll
    for (int nt = 0; nt < 8; nt++) {
        int col = h * 64 + nt * 8 + tq * 2;
        size_t r0 = (size_t)(b * SEQ + qr0) * D_MODEL + col;
        size_t r1 = (size_t)(b * SEQ + qr0 + 8) * D_MODEL + col;
#pragma unroll
        for (int half = 0; half < 2; half++) {
            size_t rr = half ? r1 : r0;
            float inv = half ? inv1 : inv0;
            float ar0 = or_[nt][half * 2 + 0] * inv;
            float ar1 = or_[nt][half * 2 + 1] * inv;
            float ai0 = oi_[nt][half * 2 + 0] * inv;
            float ai1 = oi_[nt][half * 2 + 1] * inv;
            __nv_bfloat16 h0, lo0, h1, lo1;
            bsplit(ar0, h0, lo0); bsplit(ar1, h1, lo1);
            *(uint32_t*)(g_arH + rr) = packbf2(h0, h1);
            *(uint32_t*)(g_arL + rr) = packbf2(lo0, lo1);
            bsplit(ai0, h0, lo0); bsplit(ai1, h1, lo1);
            *(uint32_t*)(g_aiH + rr) = packbf2(h0, h1);
            *(uint32_t*)(g_aiL + rr) = packbf2(lo0, lo1);
        }
    }
}

// ---------------- launch ----------------
extern "C" void kernel_launch(void* const* d_in, const int* in_sizes, int n_in,
                              void* d_out, int out_size) {
    (void)in_sizes; (void)n_in; (void)out_size;
    const float* x_re    = (const float*)d_in[0];
    const float* x_im    = (const float*)d_in[1];
    const float* wqkv_re = (const float*)d_in[2];
    const float* wqkv_im = (const float*)d_in[3];
    const float* wo_re   = (const float*)d_in[4];
    const float* wo_im   = (const float*)d_in[5];
    float* out = (float*)d_out;

    __nv_bfloat16 *xrH, *xrL, *xiH, *xiL;
    __nv_bfloat16 *wqrH, *wqrL, *wqiH, *wqiL;
    __nv_bfloat16 *worH, *worL, *woiH, *woiL;
    __nv_bfloat16 *arH, *arL, *aiH, *aiL;
    cudaGetSymbolAddress((void**)&xrH, g_xrH);   cudaGetSymbolAddress((void**)&xrL, g_xrL);
    cudaGetSymbolAddress((void**)&xiH, g_xiH);   cudaGetSymbolAddress((void**)&xiL, g_xiL);
    cudaGetSymbolAddress((void**)&wqrH, g_wqrH); cudaGetSymbolAddress((void**)&wqrL, g_wqrL);
    cudaGetSymbolAddress((void**)&wqiH, g_wqiH); cudaGetSymbolAddress((void**)&wqiL, g_wqiL);
    cudaGetSymbolAddress((void**)&worH, g_worH); cudaGetSymbolAddress((void**)&worL, g_worL);
    cudaGetSymbolAddress((void**)&woiH, g_woiH); cudaGetSymbolAddress((void**)&woiL, g_woiL);
    cudaGetSymbolAddress((void**)&arH, g_arH);   cudaGetSymbolAddress((void**)&arL, g_arL);
    cudaGetSymbolAddress((void**)&aiH, g_aiH);   cudaGetSymbolAddress((void**)&aiL, g_aiL);

    cudaFuncSetAttribute(cgemm_tc_kernel<true>,
                         cudaFuncAttributeMaxDynamicSharedMemorySize, G_SMEM);
    cudaFuncSetAttribute(cgemm_tc_kernel<false>,
                         cudaFuncAttributeMaxDynamicSharedMemorySize, G_SMEM);
    cudaFuncSetAttribute(attn_tc_kernel,
                         cudaFuncAttributeMaxDynamicSharedMemorySize, A_SMEM);

    // 1. rope table
    rope_table_kernel<<<(SEQ * D_HEAD + 255) / 256, 256>>>();

    // 2. complex hi/lo splits of inputs + weights
    split_cx_kernel<<<(XN / 4 + 255) / 256, 256>>>(x_re, x_im, xrH, xrL, xiH, xiL, XN / 4);
    split_cx_kernel<<<(WQN / 4 + 255) / 256, 256>>>(wqkv_re, wqkv_im, wqrH, wqrL, wqiH, wqiL, WQN / 4);
    split_cx_kernel<<<(WON / 4 + 255) / 256, 256>>>(wo_re, wo_im, worH, worL, woiH, woiL, WON / 4);

    // 3. QKV projection with fused RoPE + head-split + Q/K/V emit
    {
        dim3 grid(QKV_N / GBN, M_TOK / GBM);
        cgemm_tc_kernel<true><<<grid, 256, G_SMEM>>>(
            xrH, xrL, xiH, xiL, wqrH, wqrL, wqiH, wqiL,
            nullptr, nullptr, QKV_N, D_MODEL);
    }

    // 4. tensor-core flash attention (fp16 PV; emits output splits directly)
    {
        dim3 grid(SEQ / 128, BHN);
        attn_tc_kernel<<<grid, 256, A_SMEM>>>();
    }

    // 5. output projection -> d_out
    {
        dim3 grid(D_MODEL / GBN, M_TOK / GBM);
        cgemm_tc_kernel<false><<<grid, 256, G_SMEM>>>(
            arH, arL, aiH, aiL, worH, worL, woiH, woiL,
            out, out + (size_t)M_TOK * D_MODEL, D_MODEL, D_MODEL);
    }
}